// round 4
// baseline (speedup 1.0000x reference)
#include <cuda_runtime.h>
#include <cuda_bf16.h>
#include <cstdint>
#include <math.h>

#define BATCH 32
#define SEQ   512
#define DIM   512

using bf16 = __nv_bfloat16;

// ---------------- scratch (static device memory; no allocations) ------------
#define NELEM ((size_t)BATCH * SEQ * DIM)          // 8,388,608
#define WELEM ((size_t)DIM * 2 * DIM)              // 524,288
__device__ __align__(16) bf16 g_qh[NELEM], g_ql[NELEM];     // Q hi/lo      [b,q,d]
__device__ __align__(16) bf16 g_eh[NELEM], g_el[NELEM];     // Enc hi/lo    [b,e,d]
__device__ __align__(16) bf16 g_eth[NELEM], g_etl[NELEM];   // EncT hi/lo   [b,d,e]
__device__ __align__(16) bf16 g_awh[NELEM], g_awl[NELEM];   // attn weights [b,q,e]
__device__ __align__(16) bf16 g_ch[NELEM], g_cl[NELEM];     // ctx hi/lo    [b,q,d]
__device__ __align__(16) bf16 g_wh[WELEM], g_wl[WELEM];

// ---------------- PTX helpers (all non-arch-'a'; compile for sm_103) --------
__device__ __forceinline__ uint32_t smem_u32(const void* p) {
    uint32_t a;
    asm("{ .reg .u64 t; cvta.to.shared.u64 t, %1; cvt.u32.u64 %0, t; }" : "=r"(a) : "l"(p));
    return a;
}
__device__ __forceinline__ void cp16(uint32_t dst, const void* src) {
    asm volatile("cp.async.cg.shared.global [%0], [%1], 16;" :: "r"(dst), "l"(src));
}
#define CP_COMMIT() asm volatile("cp.async.commit_group;" ::: "memory")
#define CP_WAIT1()  asm volatile("cp.async.wait_group 1;" ::: "memory")

__device__ __forceinline__ void ldm4(uint32_t* r, uint32_t addr) {
    asm volatile("ldmatrix.sync.aligned.m8n8.x4.shared.b16 {%0,%1,%2,%3}, [%4];"
                 : "=r"(r[0]), "=r"(r[1]), "=r"(r[2]), "=r"(r[3]) : "r"(addr));
}
__device__ __forceinline__ void mma16816(float* c, const uint32_t* a, const uint32_t* b) {
    asm volatile(
        "mma.sync.aligned.m16n8k16.row.col.f32.bf16.bf16.f32 "
        "{%0,%1,%2,%3}, {%4,%5,%6,%7}, {%8,%9}, {%0,%1,%2,%3};"
        : "+f"(c[0]), "+f"(c[1]), "+f"(c[2]), "+f"(c[3])
        : "r"(a[0]), "r"(a[1]), "r"(a[2]), "r"(a[3]), "r"(b[0]), "r"(b[1]));
}

// ---------------- GEMM: C = A @ B^T, bf16-split (hh + hl + lh) --------------
// CTA tile 128x128, BK=32 (64B rows). 8 warps, warp tile 32(m) x 64(n).
// smem per stage: Ah, Al, Bh, Bl each 128x32 bf16 (8KB) = 32KB; 2 stages = 64KB.
// __launch_bounds__(256, 2): cap regs at 128 -> 2 CTAs/SM (128KB smem total).
#define TILE_B   8192
#define STAGE_B  (4 * TILE_B)
#define SMEM_DYN (2 * STAGE_B)
#define SB ((size_t)SEQ * DIM)

// swizzled byte offset within one tile for (row, 16B-chunk kc)
__device__ __forceinline__ uint32_t swz(int row, int kc) {
    return (uint32_t)(row * 64 + ((kc ^ ((row >> 1) & 3)) << 4));
}

// MODE 0: scores = alpha * Q @ Enc^T          -> Cf (fp32)
// MODE 1: ctx    = AW @ EncT^T                -> g_ch/g_cl (bf16 split)
// MODE 2: out    = tanh([Q|ctx] @ W^T + b)*m  -> Cf (fp32)
template <int MODE>
__global__ __launch_bounds__(256, 2) void k_gemm(
    float* __restrict__ Cf, const float* __restrict__ bias,
    const float* __restrict__ mask, float alpha)
{
    extern __shared__ char smem[];
    const uint32_t sm = smem_u32(smem);

    const int tid = threadIdx.x;
    const int lane = tid & 31, wid = tid >> 5;
    const int wm = wid & 3, wn = wid >> 2;       // 4 m-warps x 2 n-warps
    const int b  = blockIdx.z;
    const int m0 = blockIdx.y * 128;
    const int n0 = blockIdx.x * 128;

    const bf16 *Ah, *Al, *A2h = nullptr, *A2l = nullptr, *Bh, *Bl;
    int K, lda, ldb;
    if (MODE == 0) {
        Ah = g_qh + (size_t)b * SB;  Al = g_ql + (size_t)b * SB;
        Bh = g_eh + (size_t)b * SB;  Bl = g_el + (size_t)b * SB;
        K = DIM; lda = DIM; ldb = DIM;
    } else if (MODE == 1) {
        Ah = g_awh + (size_t)b * SB; Al = g_awl + (size_t)b * SB;
        Bh = g_eth + (size_t)b * SB; Bl = g_etl + (size_t)b * SB;
        K = SEQ; lda = SEQ; ldb = SEQ;
    } else {
        Ah = g_qh;  Al = g_ql;       // rows indexed by global m (0..16383)
        A2h = g_ch; A2l = g_cl;
        Bh = g_wh;  Bl = g_wl;
        K = 2 * DIM; lda = DIM; ldb = 2 * DIM;
    }
    const int C = K >> 5;   // chunks of 32

    // ---- load: 4 tiles x 512 16B-chunks, 256 threads -> 2 chunks/tile/thread
#define LOAD_CHUNK(c, stg)                                                       \
    do {                                                                         \
        const int k0_ = (c) * 32;                                                \
        const bf16 *ah_, *al_; int ka_;                                          \
        if (MODE == 2 && k0_ >= DIM) { ah_ = A2h; al_ = A2l; ka_ = k0_ - DIM; }  \
        else                         { ah_ = Ah;  al_ = Al;  ka_ = k0_; }        \
        const uint32_t sb_ = sm + (stg) * STAGE_B;                               \
        _Pragma("unroll")                                                        \
        for (int i_ = 0; i_ < 2; i_++) {                                         \
            int idx_ = i_ * 256 + tid;                                           \
            int row_ = idx_ >> 2, kc_ = idx_ & 3;                                \
            uint32_t d_ = swz(row_, kc_);                                        \
            const char* pa_ = (const char*)(ah_ + (size_t)(m0 + row_) * lda + ka_) + kc_ * 16; \
            const char* pl_ = (const char*)(al_ + (size_t)(m0 + row_) * lda + ka_) + kc_ * 16; \
            const char* pb_ = (const char*)(Bh + (size_t)(n0 + row_) * ldb + k0_) + kc_ * 16;  \
            const char* pc_ = (const char*)(Bl + (size_t)(n0 + row_) * ldb + k0_) + kc_ * 16;  \
            cp16(sb_ + d_, pa_);                                                 \
            cp16(sb_ + TILE_B + d_, pl_);                                        \
            cp16(sb_ + 2 * TILE_B + d_, pb_);                                    \
            cp16(sb_ + 3 * TILE_B + d_, pc_);                                    \
        }                                                                        \
    } while (0)

    // ---- per-lane ldmatrix address precomputes
    const int ar = lane & 15, ktop = lane >> 4;
    int aoff[2], axr[2];
#pragma unroll
    for (int mi = 0; mi < 2; mi++) {
        int row = wm * 32 + mi * 16 + ar;
        aoff[mi] = row * 64; axr[mi] = (row >> 1) & 3;
    }
    const int bmat = lane >> 3;
    const int bkadd = bmat & 1;
    const int brl = ((bmat >> 1) << 3) + (lane & 7);
    int boff[4], bxr[4];
#pragma unroll
    for (int g = 0; g < 4; g++) {
        int nrow = wn * 64 + g * 16 + brl;
        boff[g] = nrow * 64; bxr[g] = (nrow >> 1) & 3;
    }

    float acc[2][8][4];
#pragma unroll
    for (int i = 0; i < 2; i++)
#pragma unroll
        for (int j = 0; j < 8; j++)
#pragma unroll
            for (int q = 0; q < 4; q++) acc[i][j][q] = 0.f;

    LOAD_CHUNK(0, 0); CP_COMMIT();
    LOAD_CHUNK(1, 1); CP_COMMIT();

    for (int c = 0; c < C; c++) {
        CP_WAIT1();
        __syncthreads();
        const uint32_t sb = sm + (c & 1) * STAGE_B;
#pragma unroll
        for (int ks = 0; ks < 2; ks++) {
            const int kb = ks * 2;
            uint32_t afr[2][2][4];
#pragma unroll
            for (int mi = 0; mi < 2; mi++)
#pragma unroll
                for (int v = 0; v < 2; v++)
                    ldm4(afr[mi][v],
                         sb + v * TILE_B + aoff[mi] + (((kb + ktop) ^ axr[mi]) << 4));
            uint32_t bfr[4][2][4];
#pragma unroll
            for (int g = 0; g < 4; g++)
#pragma unroll
                for (int v = 0; v < 2; v++)
                    ldm4(bfr[g][v],
                         sb + (2 + v) * TILE_B + boff[g] + (((kb + bkadd) ^ bxr[g]) << 4));
#pragma unroll
            for (int mi = 0; mi < 2; mi++)
#pragma unroll
                for (int nj = 0; nj < 8; nj++) {
                    const int g = nj >> 1, h = (nj & 1) * 2;
                    mma16816(acc[mi][nj], afr[mi][0], &bfr[g][0][h]);  // hh
                    mma16816(acc[mi][nj], afr[mi][0], &bfr[g][1][h]);  // h*l
                    mma16816(acc[mi][nj], afr[mi][1], &bfr[g][0][h]);  // l*h
                }
        }
        __syncthreads();
        if (c + 2 < C) LOAD_CHUNK(c + 2, c & 1);
        CP_COMMIT();
    }
#undef LOAD_CHUNK

    // ---- epilogue from registers
    const int qr = lane >> 2, qc = lane & 3;
#pragma unroll
    for (int mi = 0; mi < 2; mi++)
#pragma unroll
        for (int nj = 0; nj < 8; nj++)
#pragma unroll
            for (int half = 0; half < 2; half++) {
                const int row = m0 + wm * 32 + mi * 16 + qr + half * 8;
                const int col = n0 + wn * 64 + nj * 8 + qc * 2;
                const float v0 = acc[mi][nj][half * 2 + 0];
                const float v1 = acc[mi][nj][half * 2 + 1];
                if (MODE == 0) {
                    float2 o = make_float2(v0 * alpha, v1 * alpha);
                    *(float2*)(Cf + (size_t)b * SEQ * SEQ + (size_t)row * SEQ + col) = o;
                } else if (MODE == 1) {
                    size_t o = (size_t)b * SB + (size_t)row * DIM + col;
                    __nv_bfloat162 H, L;
                    H.x = __float2bfloat16_rn(v0);
                    H.y = __float2bfloat16_rn(v1);
                    L.x = __float2bfloat16_rn(v0 - __bfloat162float(H.x));
                    L.y = __float2bfloat16_rn(v1 - __bfloat162float(H.y));
                    *(__nv_bfloat162*)(g_ch + o) = H;
                    *(__nv_bfloat162*)(g_cl + o) = L;
                } else {
                    const float mk = mask[row];
                    float2 o = make_float2(tanhf(v0 + bias[col]) * mk,
                                           tanhf(v1 + bias[col + 1]) * mk);
                    *(float2*)(Cf + (size_t)row * DIM + col) = o;
                }
            }
}

// ------ fp32 -> bf16 hi/lo split: Q and W fused in one grid (x4 vec) --------
#define NQ4 (NELEM / 4)
#define NW4 (WELEM / 4)
__global__ __launch_bounds__(256) void k_split_qw(const float4* __restrict__ Qs,
                                                  const float4* __restrict__ Ws)
{
    int i = blockIdx.x * 256 + threadIdx.x;
    const float4* src;
    uint2 *hi, *lo;
    int j;
    if (i < NQ4) { src = Qs; hi = (uint2*)g_qh; lo = (uint2*)g_ql; j = i; }
    else if (i < NQ4 + NW4) { src = Ws; hi = (uint2*)g_wh; lo = (uint2*)g_wl; j = i - NQ4; }
    else return;
    float4 v = src[j];
    union { bf16 h[4]; uint2 u; } H, L;
    H.h[0] = __float2bfloat16_rn(v.x); L.h[0] = __float2bfloat16_rn(v.x - __bfloat162float(H.h[0]));
    H.h[1] = __float2bfloat16_rn(v.y); L.h[1] = __float2bfloat16_rn(v.y - __bfloat162float(H.h[1]));
    H.h[2] = __float2bfloat16_rn(v.z); L.h[2] = __float2bfloat16_rn(v.z - __bfloat162float(H.h[2]));
    H.h[3] = __float2bfloat16_rn(v.w); L.h[3] = __float2bfloat16_rn(v.w - __bfloat162float(H.h[3]));
    hi[j] = H.u; lo[j] = L.u;
}

// ------- Enc: split (plain) + split-transpose (per batch, 32x32 tiles) ------
__global__ __launch_bounds__(1024) void k_split_trans(const float* __restrict__ E)
{
    __shared__ float t[32][33];
    const int b = blockIdx.z, e0 = blockIdx.y * 32, d0 = blockIdx.x * 32;
    const int tx = threadIdx.x, ty = threadIdx.y;
    const float* Eb = E + (size_t)b * SB;

    float v = Eb[(size_t)(e0 + ty) * DIM + d0 + tx];
    size_t o = (size_t)b * SB + (size_t)(e0 + ty) * DIM + d0 + tx;
    bf16 h = __float2bfloat16_rn(v);
    g_eh[o] = h;
    g_el[o] = __float2bfloat16_rn(v - __bfloat162float(h));
    t[ty][tx] = v;
    __syncthreads();
    float u = t[tx][ty];
    size_t ot = (size_t)b * SB + (size_t)(d0 + ty) * SEQ + e0 + tx;
    bf16 hh = __float2bfloat16_rn(u);
    g_eth[ot] = hh;
    g_etl[ot] = __float2bfloat16_rn(u - __bfloat162float(hh));
}

// ---------------- softmax (in place) + bf16 hi/lo split out -----------------
__global__ __launch_bounds__(256) void k_softmax_split(float* __restrict__ w)
{
    float* row = w + (size_t)blockIdx.x * SEQ;
    const int t = threadIdx.x;
    float a = row[t];
    float b = row[t + 256];

    __shared__ float red[8];
    float m = fmaxf(a, b);
#pragma unroll
    for (int o = 16; o > 0; o >>= 1) m = fmaxf(m, __shfl_xor_sync(0xffffffffu, m, o));
    if ((t & 31) == 0) red[t >> 5] = m;
    __syncthreads();
    float M = fmaxf(fmaxf(fmaxf(red[0], red[1]), fmaxf(red[2], red[3])),
                    fmaxf(fmaxf(red[4], red[5]), fmaxf(red[6], red[7])));
    __syncthreads();
    float e0 = __expf(a - M), e1 = __expf(b - M);
    float s = e0 + e1;
#pragma unroll
    for (int o = 16; o > 0; o >>= 1) s += __shfl_xor_sync(0xffffffffu, s, o);
    if ((t & 31) == 0) red[t >> 5] = s;
    __syncthreads();
    float S = red[0] + red[1] + red[2] + red[3] + red[4] + red[5] + red[6] + red[7];

    float inv = 1.0f / S;
    float v0 = e0 * inv, v1 = e1 * inv;
    row[t] = v0;
    row[t + 256] = v1;

    size_t base = (size_t)blockIdx.x * SEQ;
    bf16 h0 = __float2bfloat16_rn(v0);
    bf16 h1 = __float2bfloat16_rn(v1);
    g_awh[base + t] = h0;
    g_awl[base + t] = __float2bfloat16_rn(v0 - __bfloat162float(h0));
    g_awh[base + t + 256] = h1;
    g_awl[base + t + 256] = __float2bfloat16_rn(v1 - __bfloat162float(h1));
}

// ---------------------------------------------------------------------------
extern "C" void kernel_launch(void* const* d_in, const int* in_sizes, int n_in,
                              void* d_out, int out_size)
{
    const float* Q    = (const float*)d_in[0];
    const float* Enc  = (const float*)d_in[1];
    const float* mask = (const float*)d_in[2];
    const float* W    = (const float*)d_in[3];
    const float* bias = (const float*)d_in[4];

    float* out_masked  = (float*)d_out;
    float* out_weights = (float*)d_out + NELEM;

    static bool attr_done = false;
    if (!attr_done) {
        cudaFuncSetAttribute(k_gemm<0>, cudaFuncAttributeMaxDynamicSharedMemorySize, SMEM_DYN);
        cudaFuncSetAttribute(k_gemm<1>, cudaFuncAttributeMaxDynamicSharedMemorySize, SMEM_DYN);
        cudaFuncSetAttribute(k_gemm<2>, cudaFuncAttributeMaxDynamicSharedMemorySize, SMEM_DYN);
        attr_done = true;
    }

    const float alpha = 1.0f / sqrtf((float)DIM);

    // 1) splits (Q + W fused; Enc split + transpose)
    {
        int total = (int)(NQ4 + NW4);
        k_split_qw<<<(total + 255) / 256, 256>>>((const float4*)Q, (const float4*)W);
    }
    {
        dim3 g(DIM / 32, SEQ / 32, BATCH), blk(32, 32);
        k_split_trans<<<g, blk>>>(Enc);
    }

    // 2) scores = alpha * Q @ Enc^T -> out_weights (fp32)
    {
        dim3 g(SEQ / 128, SEQ / 128, BATCH);
        k_gemm<0><<<g, 256, SMEM_DYN>>>(out_weights, nullptr, nullptr, alpha);
    }
    // 3) softmax + split
    k_softmax_split<<<BATCH * SEQ, 256>>>(out_weights);
    // 4) ctx = AW @ EncT^T -> g_ch/g_cl
    {
        dim3 g(DIM / 128, SEQ / 128, BATCH);
        k_gemm<1><<<g, 256, SMEM_DYN>>>(nullptr, nullptr, nullptr, 1.0f);
    }
    // 5) out = tanh([Q|ctx] @ W^T + bias) * mask
    {
        dim3 g(DIM / 128, (BATCH * SEQ) / 128, 1);
        k_gemm<2><<<g, 256, SMEM_DYN>>>(out_masked, bias, mask, 1.0f);
    }
}

// round 5
// speedup vs baseline: 1.5339x; 1.5339x over previous
#include <cuda_runtime.h>
#include <cuda_bf16.h>
#include <cstdint>
#include <math.h>

#define BATCH 32
#define SEQ   512
#define DIM   512

using bf16 = __nv_bfloat16;

// ---------------- scratch (static device memory; no allocations) ------------
#define NELEM ((size_t)BATCH * SEQ * DIM)          // 8,388,608
#define WELEM ((size_t)DIM * 2 * DIM)              // 524,288
__device__ __align__(16) bf16 g_qh[NELEM], g_ql[NELEM];     // Q hi/lo      [b,q,d]
__device__ __align__(16) bf16 g_eh[NELEM], g_el[NELEM];     // Enc hi/lo    [b,e,d]
__device__ __align__(16) bf16 g_eth[NELEM], g_etl[NELEM];   // EncT hi/lo   [b,d,e]
__device__ __align__(16) bf16 g_awh[NELEM], g_awl[NELEM];   // attn weights [b,q,e]
__device__ __align__(16) bf16 g_ch[NELEM], g_cl[NELEM];     // ctx hi/lo    [b,q,d]
__device__ __align__(16) bf16 g_wh[WELEM], g_wl[WELEM];

// ---------------- PTX helpers (all non-arch-'a'; compile for sm_103) --------
__device__ __forceinline__ uint32_t smem_u32(const void* p) {
    uint32_t a;
    asm("{ .reg .u64 t; cvta.to.shared.u64 t, %1; cvt.u32.u64 %0, t; }" : "=r"(a) : "l"(p));
    return a;
}
__device__ __forceinline__ void cp16(uint32_t dst, const void* src) {
    asm volatile("cp.async.cg.shared.global [%0], [%1], 16;" :: "r"(dst), "l"(src));
}
#define CP_COMMIT() asm volatile("cp.async.commit_group;" ::: "memory")
#define CP_WAIT1()  asm volatile("cp.async.wait_group 1;" ::: "memory")

__device__ __forceinline__ void ldm4(uint32_t* r, uint32_t addr) {
    asm volatile("ldmatrix.sync.aligned.m8n8.x4.shared.b16 {%0,%1,%2,%3}, [%4];"
                 : "=r"(r[0]), "=r"(r[1]), "=r"(r[2]), "=r"(r[3]) : "r"(addr));
}
__device__ __forceinline__ void ldm2(uint32_t* r, uint32_t addr) {
    asm volatile("ldmatrix.sync.aligned.m8n8.x2.shared.b16 {%0,%1}, [%2];"
                 : "=r"(r[0]), "=r"(r[1]) : "r"(addr));
}
__device__ __forceinline__ void mma16816(float* c, const uint32_t* a, const uint32_t* b) {
    asm volatile(
        "mma.sync.aligned.m16n8k16.row.col.f32.bf16.bf16.f32 "
        "{%0,%1,%2,%3}, {%4,%5,%6,%7}, {%8,%9}, {%0,%1,%2,%3};"
        : "+f"(c[0]), "+f"(c[1]), "+f"(c[2]), "+f"(c[3])
        : "r"(a[0]), "r"(a[1]), "r"(a[2]), "r"(a[3]), "r"(b[0]), "r"(b[1]));
}

// ---------------- GEMM: C = A @ B^T, bf16-split (hh + hl + lh) --------------
// CTA tile 128x128, BK=32 (64B rows). 8 warps, warp tile 32(m) x 64(n).
// smem per stage: Ah, Al, Bh, Bl each 128x32 bf16 (8KB) = 32KB; 3 stages = 96KB.
// B fragments loaded per-n-group to keep live regs < 128 -> 2 CTAs/SM.
#define TILE_B   8192
#define STAGE_B  (4 * TILE_B)
#define NSTAGE   3
#define SMEM_DYN (NSTAGE * STAGE_B)
#define SB ((size_t)SEQ * DIM)

// swizzled byte offset within one tile for (row, 16B-chunk kc)
__device__ __forceinline__ uint32_t swz(int row, int kc) {
    return (uint32_t)(row * 64 + ((kc ^ ((row >> 1) & 3)) << 4));
}

// MODE 0: scores = alpha * Q @ Enc^T          -> Cf (fp32)
// MODE 1: ctx    = AW @ EncT^T                -> g_ch/g_cl (bf16 split)
// MODE 2: out    = tanh([Q|ctx] @ W^T + b)*m  -> Cf (fp32)
template <int MODE>
__global__ __launch_bounds__(256, 2) void k_gemm(
    float* __restrict__ Cf, const float* __restrict__ bias,
    const float* __restrict__ mask, float alpha)
{
    extern __shared__ char smem[];
    const uint32_t sm = smem_u32(smem);

    const int tid = threadIdx.x;
    const int lane = tid & 31, wid = tid >> 5;
    const int wm = wid & 3, wn = wid >> 2;       // 4 m-warps x 2 n-warps
    const int b  = blockIdx.z;
    const int m0 = blockIdx.y * 128;
    const int n0 = blockIdx.x * 128;

    const bf16 *Ah, *Al, *A2h = nullptr, *A2l = nullptr, *Bh, *Bl;
    int K, lda, ldb;
    if (MODE == 0) {
        Ah = g_qh + (size_t)b * SB;  Al = g_ql + (size_t)b * SB;
        Bh = g_eh + (size_t)b * SB;  Bl = g_el + (size_t)b * SB;
        K = DIM; lda = DIM; ldb = DIM;
    } else if (MODE == 1) {
        Ah = g_awh + (size_t)b * SB; Al = g_awl + (size_t)b * SB;
        Bh = g_eth + (size_t)b * SB; Bl = g_etl + (size_t)b * SB;
        K = SEQ; lda = SEQ; ldb = SEQ;
    } else {
        Ah = g_qh;  Al = g_ql;       // rows indexed by global m (0..16383)
        A2h = g_ch; A2l = g_cl;
        Bh = g_wh;  Bl = g_wl;
        K = 2 * DIM; lda = DIM; ldb = 2 * DIM;
    }
    const int C = K >> 5;   // chunks of 32

    // ---- load: 4 tiles x 512 16B-chunks, 256 threads -> 2 chunks/tile/thread
#define LOAD_CHUNK(c, stg)                                                       \
    do {                                                                         \
        const int k0_ = (c) * 32;                                                \
        const bf16 *ah_, *al_; int ka_;                                          \
        if (MODE == 2 && k0_ >= DIM) { ah_ = A2h; al_ = A2l; ka_ = k0_ - DIM; }  \
        else                         { ah_ = Ah;  al_ = Al;  ka_ = k0_; }        \
        const uint32_t sb_ = sm + (stg) * STAGE_B;                               \
        _Pragma("unroll")                                                        \
        for (int i_ = 0; i_ < 2; i_++) {                                         \
            int idx_ = i_ * 256 + tid;                                           \
            int row_ = idx_ >> 2, kc_ = idx_ & 3;                                \
            uint32_t d_ = swz(row_, kc_);                                        \
            const char* pa_ = (const char*)(ah_ + (size_t)(m0 + row_) * lda + ka_) + kc_ * 16; \
            const char* pl_ = (const char*)(al_ + (size_t)(m0 + row_) * lda + ka_) + kc_ * 16; \
            const char* pb_ = (const char*)(Bh + (size_t)(n0 + row_) * ldb + k0_) + kc_ * 16;  \
            const char* pc_ = (const char*)(Bl + (size_t)(n0 + row_) * ldb + k0_) + kc_ * 16;  \
            cp16(sb_ + d_, pa_);                                                 \
            cp16(sb_ + TILE_B + d_, pl_);                                        \
            cp16(sb_ + 2 * TILE_B + d_, pb_);                                    \
            cp16(sb_ + 3 * TILE_B + d_, pc_);                                    \
        }                                                                        \
    } while (0)

    // ---- per-lane ldmatrix address precomputes
    const int ar = lane & 15, ktop = lane >> 4;
    int aoff[2], axr[2];
#pragma unroll
    for (int mi = 0; mi < 2; mi++) {
        int row = wm * 32 + mi * 16 + ar;
        aoff[mi] = row * 64; axr[mi] = (row >> 1) & 3;
    }
    // x2 ldmatrix for B: 2 matrices (n8 x 2 along k); lane>>4 selects k-half
    const int brl = ((lane >> 4) << 3) + (lane & 7);  // row for x2 load
    const int bk2 = (lane >> 3) & 1;                  // k-16B selector within pair
    int boff[4], bxr[4];
#pragma unroll
    for (int g = 0; g < 4; g++) {
        int nrow = wn * 64 + g * 16 + brl;
        boff[g] = nrow * 64; bxr[g] = (nrow >> 1) & 3;
    }

    float acc[2][8][4];
#pragma unroll
    for (int i = 0; i < 2; i++)
#pragma unroll
        for (int j = 0; j < 8; j++)
#pragma unroll
            for (int q = 0; q < 4; q++) acc[i][j][q] = 0.f;

    LOAD_CHUNK(0, 0); CP_COMMIT();
    LOAD_CHUNK(1, 1); CP_COMMIT();

    for (int c = 0; c < C; c++) {
        CP_WAIT1();
        __syncthreads();                 // stage c ready; all warps done with stage (c-1)%3
        if (c + 2 < C) { LOAD_CHUNK(c + 2, (c + 2) % NSTAGE); }
        CP_COMMIT();
        const uint32_t sb = sm + (c % NSTAGE) * STAGE_B;
#pragma unroll
        for (int ks = 0; ks < 2; ks++) {
            const int kb = ks * 2;
            uint32_t afr[2][2][4];
#pragma unroll
            for (int mi = 0; mi < 2; mi++)
#pragma unroll
                for (int v = 0; v < 2; v++)
                    ldm4(afr[mi][v],
                         sb + v * TILE_B + aoff[mi] + (((kb + ktop) ^ axr[mi]) << 4));
#pragma unroll
            for (int g = 0; g < 4; g++) {
                // B fragments for this n-group only: 16 n-rows x k16, hi & lo
                uint32_t bh[4], bl[4];
                {
                    // x4 would fetch both k-halves for 16 rows; we need the
                    // (kb..kb+1) 16B chunks: each x4 covers rows 0..15 at one
                    // 16-bit column block. Use two x2 loads (one per 8-row pair
                    // along k) -> 4 regs each for hi and lo.
                    uint32_t a0 = sb + 2 * TILE_B + boff[g] + (((kb + bk2) ^ bxr[g]) << 4);
                    uint32_t a1 = sb + 3 * TILE_B + boff[g] + (((kb + bk2) ^ bxr[g]) << 4);
                    ldm4(bh, a0);
                    ldm4(bl, a1);
                }
#pragma unroll
                for (int half = 0; half < 2; half++) {
                    const int nj = g * 2 + half;
                    const int h = half * 2;
#pragma unroll
                    for (int mi = 0; mi < 2; mi++) {
                        mma16816(acc[mi][nj], afr[mi][0], &bh[h]);  // hh
                        mma16816(acc[mi][nj], afr[mi][0], &bl[h]);  // h*l
                        mma16816(acc[mi][nj], afr[mi][1], &bh[h]);  // l*h
                    }
                }
            }
        }
    }
#undef LOAD_CHUNK

    // ---- epilogue from registers
    const int qr = lane >> 2, qc = lane & 3;
#pragma unroll
    for (int mi = 0; mi < 2; mi++)
#pragma unroll
        for (int nj = 0; nj < 8; nj++)
#pragma unroll
            for (int half = 0; half < 2; half++) {
                const int row = m0 + wm * 32 + mi * 16 + qr + half * 8;
                const int col = n0 + wn * 64 + nj * 8 + qc * 2;
                const float v0 = acc[mi][nj][half * 2 + 0];
                const float v1 = acc[mi][nj][half * 2 + 1];
                if (MODE == 0) {
                    float2 o = make_float2(v0 * alpha, v1 * alpha);
                    *(float2*)(Cf + (size_t)b * SEQ * SEQ + (size_t)row * SEQ + col) = o;
                } else if (MODE == 1) {
                    size_t o = (size_t)b * SB + (size_t)row * DIM + col;
                    __nv_bfloat162 H, L;
                    H.x = __float2bfloat16_rn(v0);
                    H.y = __float2bfloat16_rn(v1);
                    L.x = __float2bfloat16_rn(v0 - __bfloat162float(H.x));
                    L.y = __float2bfloat16_rn(v1 - __bfloat162float(H.y));
                    *(__nv_bfloat162*)(g_ch + o) = H;
                    *(__nv_bfloat162*)(g_cl + o) = L;
                } else {
                    const float mk = mask[row];
                    float2 o = make_float2(tanhf(v0 + bias[col]) * mk,
                                           tanhf(v1 + bias[col + 1]) * mk);
                    *(float2*)(Cf + (size_t)row * DIM + col) = o;
                }
            }
}

// ------ fp32 -> bf16 hi/lo split: Q and W fused in one grid (x4 vec) --------
#define NQ4 (NELEM / 4)
#define NW4 (WELEM / 4)
__global__ __launch_bounds__(256) void k_split_qw(const float4* __restrict__ Qs,
                                                  const float4* __restrict__ Ws)
{
    int i = blockIdx.x * 256 + threadIdx.x;
    const float4* src;
    uint2 *hi, *lo;
    int j;
    if (i < NQ4) { src = Qs; hi = (uint2*)g_qh; lo = (uint2*)g_ql; j = i; }
    else if (i < NQ4 + NW4) { src = Ws; hi = (uint2*)g_wh; lo = (uint2*)g_wl; j = i - NQ4; }
    else return;
    float4 v = src[j];
    union { bf16 h[4]; uint2 u; } H, L;
    H.h[0] = __float2bfloat16_rn(v.x); L.h[0] = __float2bfloat16_rn(v.x - __bfloat162float(H.h[0]));
    H.h[1] = __float2bfloat16_rn(v.y); L.h[1] = __float2bfloat16_rn(v.y - __bfloat162float(H.h[1]));
    H.h[2] = __float2bfloat16_rn(v.z); L.h[2] = __float2bfloat16_rn(v.z - __bfloat162float(H.h[2]));
    H.h[3] = __float2bfloat16_rn(v.w); L.h[3] = __float2bfloat16_rn(v.w - __bfloat162float(H.h[3]));
    hi[j] = H.u; lo[j] = L.u;
}

// ------- Enc: split (plain) + split-transpose (per batch, 32x32 tiles) ------
__global__ __launch_bounds__(1024) void k_split_trans(const float* __restrict__ E)
{
    __shared__ float t[32][33];
    const int b = blockIdx.z, e0 = blockIdx.y * 32, d0 = blockIdx.x * 32;
    const int tx = threadIdx.x, ty = threadIdx.y;
    const float* Eb = E + (size_t)b * SB;

    float v = Eb[(size_t)(e0 + ty) * DIM + d0 + tx];
    size_t o = (size_t)b * SB + (size_t)(e0 + ty) * DIM + d0 + tx;
    bf16 h = __float2bfloat16_rn(v);
    g_eh[o] = h;
    g_el[o] = __float2bfloat16_rn(v - __bfloat162float(h));
    t[ty][tx] = v;
    __syncthreads();
    float u = t[tx][ty];
    size_t ot = (size_t)b * SB + (size_t)(d0 + ty) * SEQ + e0 + tx;
    bf16 hh = __float2bfloat16_rn(u);
    g_eth[ot] = hh;
    g_etl[ot] = __float2bfloat16_rn(u - __bfloat162float(hh));
}

// ---------------- softmax (in place) + bf16 hi/lo split out -----------------
__global__ __launch_bounds__(256) void k_softmax_split(float* __restrict__ w)
{
    float* row = w + (size_t)blockIdx.x * SEQ;
    const int t = threadIdx.x;
    float a = row[t];
    float b = row[t + 256];

    __shared__ float red[8];
    float m = fmaxf(a, b);
#pragma unroll
    for (int o = 16; o > 0; o >>= 1) m = fmaxf(m, __shfl_xor_sync(0xffffffffu, m, o));
    if ((t & 31) == 0) red[t >> 5] = m;
    __syncthreads();
    float M = fmaxf(fmaxf(fmaxf(red[0], red[1]), fmaxf(red[2], red[3])),
                    fmaxf(fmaxf(red[4], red[5]), fmaxf(red[6], red[7])));
    __syncthreads();
    float e0 = __expf(a - M), e1 = __expf(b - M);
    float s = e0 + e1;
#pragma unroll
    for (int o = 16; o > 0; o >>= 1) s += __shfl_xor_sync(0xffffffffu, s, o);
    if ((t & 31) == 0) red[t >> 5] = s;
    __syncthreads();
    float S = red[0] + red[1] + red[2] + red[3] + red[4] + red[5] + red[6] + red[7];

    float inv = 1.0f / S;
    float v0 = e0 * inv, v1 = e1 * inv;
    row[t] = v0;
    row[t + 256] = v1;

    size_t base = (size_t)blockIdx.x * SEQ;
    bf16 h0 = __float2bfloat16_rn(v0);
    bf16 h1 = __float2bfloat16_rn(v1);
    g_awh[base + t] = h0;
    g_awl[base + t] = __float2bfloat16_rn(v0 - __bfloat162float(h0));
    g_awh[base + t + 256] = h1;
    g_awl[base + t + 256] = __float2bfloat16_rn(v1 - __bfloat162float(h1));
}

// ---------------------------------------------------------------------------
extern "C" void kernel_launch(void* const* d_in, const int* in_sizes, int n_in,
                              void* d_out, int out_size)
{
    const float* Q    = (const float*)d_in[0];
    const float* Enc  = (const float*)d_in[1];
    const float* mask = (const float*)d_in[2];
    const float* W    = (const float*)d_in[3];
    const float* bias = (const float*)d_in[4];

    float* out_masked  = (float*)d_out;
    float* out_weights = (float*)d_out + NELEM;

    static bool attr_done = false;
    if (!attr_done) {
        cudaFuncSetAttribute(k_gemm<0>, cudaFuncAttributeMaxDynamicSharedMemorySize, SMEM_DYN);
        cudaFuncSetAttribute(k_gemm<1>, cudaFuncAttributeMaxDynamicSharedMemorySize, SMEM_DYN);
        cudaFuncSetAttribute(k_gemm<2>, cudaFuncAttributeMaxDynamicSharedMemorySize, SMEM_DYN);
        attr_done = true;
    }

    const float alpha = 1.0f / sqrtf((float)DIM);

    // 1) splits (Q + W fused; Enc split + transpose)
    {
        int total = (int)(NQ4 + NW4);
        k_split_qw<<<(total + 255) / 256, 256>>>((const float4*)Q, (const float4*)W);
    }
    {
        dim3 g(DIM / 32, SEQ / 32, BATCH), blk(32, 32);
        k_split_trans<<<g, blk>>>(Enc);
    }

    // 2) scores = alpha * Q @ Enc^T -> out_weights (fp32)
    {
        dim3 g(SEQ / 128, SEQ / 128, BATCH);
        k_gemm<0><<<g, 256, SMEM_DYN>>>(out_weights, nullptr, nullptr, alpha);
    }
    // 3) softmax + split
    k_softmax_split<<<BATCH * SEQ, 256>>>(out_weights);
    // 4) ctx = AW @ EncT^T -> g_ch/g_cl
    {
        dim3 g(DIM / 128, SEQ / 128, BATCH);
        k_gemm<1><<<g, 256, SMEM_DYN>>>(nullptr, nullptr, nullptr, 1.0f);
    }
    // 5) out = tanh([Q|ctx] @ W^T + bias) * mask
    {
        dim3 g(DIM / 128, (BATCH * SEQ) / 128, 1);
        k_gemm<2><<<g, 256, SMEM_DYN>>>(out_masked, bias, mask, 1.0f);
    }
}

// round 6
// speedup vs baseline: 1.6858x; 1.0990x over previous
#include <cuda_runtime.h>
#include <cuda_bf16.h>
#include <cstdint>
#include <math.h>

#define BATCH 32
#define SEQ   512
#define DIM   512

using bf16 = __nv_bfloat16;

// ---------------- scratch (static device memory; no allocations) ------------
#define NELEM ((size_t)BATCH * SEQ * DIM)          // 8,388,608
#define WELEM ((size_t)DIM * 2 * DIM)              // 524,288
__device__ __align__(16) bf16 g_qh[NELEM], g_ql[NELEM];     // Q hi/lo      [b,q,d]
__device__ __align__(16) bf16 g_eh[NELEM], g_el[NELEM];     // Enc hi/lo    [b,e,d]
__device__ __align__(16) bf16 g_awh[NELEM], g_awl[NELEM];   // attn weights [b,q,e]
__device__ __align__(16) bf16 g_ch[NELEM], g_cl[NELEM];     // ctx hi/lo    [b,q,d]
__device__ __align__(16) bf16 g_wh[WELEM], g_wl[WELEM];

// ---------------- PTX helpers (all non-arch-'a'; compile for sm_103) --------
__device__ __forceinline__ uint32_t smem_u32(const void* p) {
    uint32_t a;
    asm("{ .reg .u64 t; cvta.to.shared.u64 t, %1; cvt.u32.u64 %0, t; }" : "=r"(a) : "l"(p));
    return a;
}
__device__ __forceinline__ void cp16(uint32_t dst, const void* src) {
    asm volatile("cp.async.cg.shared.global [%0], [%1], 16;" :: "r"(dst), "l"(src));
}
#define CP_COMMIT() asm volatile("cp.async.commit_group;" ::: "memory")
#define CP_WAIT1()  asm volatile("cp.async.wait_group 1;" ::: "memory")

__device__ __forceinline__ void ldm4(uint32_t* r, uint32_t addr) {
    asm volatile("ldmatrix.sync.aligned.m8n8.x4.shared.b16 {%0,%1,%2,%3}, [%4];"
                 : "=r"(r[0]), "=r"(r[1]), "=r"(r[2]), "=r"(r[3]) : "r"(addr));
}
__device__ __forceinline__ void ldm4t(uint32_t* r, uint32_t addr) {
    asm volatile("ldmatrix.sync.aligned.m8n8.x4.trans.shared.b16 {%0,%1,%2,%3}, [%4];"
                 : "=r"(r[0]), "=r"(r[1]), "=r"(r[2]), "=r"(r[3]) : "r"(addr));
}
__device__ __forceinline__ void mma16816(float* c, const uint32_t* a, const uint32_t* b) {
    asm volatile(
        "mma.sync.aligned.m16n8k16.row.col.f32.bf16.bf16.f32 "
        "{%0,%1,%2,%3}, {%4,%5,%6,%7}, {%8,%9}, {%0,%1,%2,%3};"
        : "+f"(c[0]), "+f"(c[1]), "+f"(c[2]), "+f"(c[3])
        : "r"(a[0]), "r"(a[1]), "r"(a[2]), "r"(a[3]), "r"(b[0]), "r"(b[1]));
}

// ---------------- GEMM: C = A @ B^T, bf16-split (hh + hl + lh) --------------
// CTA tile 128x128, BK=32. 8 warps, warp tile 32(m) x 64(n). 3-stage cp.async.
// MODE 1 feeds B via ldmatrix.trans from plain [e][d] Enc tiles (no EncT).
#define TILE_B   8192
#define STAGE_B  (4 * TILE_B)
#define NSTAGE   3
#define SMEM_DYN (NSTAGE * STAGE_B)
#define SB ((size_t)SEQ * DIM)

// swizzled byte offset within one NT tile for (row, 16B-chunk kc), 64B rows
__device__ __forceinline__ uint32_t swz(int row, int kc) {
    return (uint32_t)(row * 64 + ((kc ^ ((row >> 1) & 3)) << 4));
}

// MODE 0: scores = alpha * Q @ Enc^T          -> Cf (fp32)
// MODE 1: ctx    = AW @ Enc  (trans-B)        -> g_ch/g_cl (bf16 split)
// MODE 2: out    = tanh([Q|ctx] @ W^T + b)*m  -> Cf (fp32)
template <int MODE>
__global__ __launch_bounds__(256, 2) void k_gemm(
    float* __restrict__ Cf, const float* __restrict__ bias,
    const float* __restrict__ mask, float alpha)
{
    extern __shared__ char smem[];
    const uint32_t sm = smem_u32(smem);

    const int tid = threadIdx.x;
    const int lane = tid & 31, wid = tid >> 5;
    const int wm = wid & 3, wn = wid >> 2;       // 4 m-warps x 2 n-warps
    const int b  = blockIdx.z;
    const int m0 = blockIdx.y * 128;
    const int n0 = blockIdx.x * 128;

    const bf16 *Ah, *Al, *A2h = nullptr, *A2l = nullptr, *Bh, *Bl;
    int K, lda, ldb;
    if (MODE == 0) {
        Ah = g_qh + (size_t)b * SB;  Al = g_ql + (size_t)b * SB;
        Bh = g_eh + (size_t)b * SB;  Bl = g_el + (size_t)b * SB;
        K = DIM; lda = DIM; ldb = DIM;
    } else if (MODE == 1) {
        Ah = g_awh + (size_t)b * SB; Al = g_awl + (size_t)b * SB;
        Bh = g_eh + (size_t)b * SB;  Bl = g_el + (size_t)b * SB;   // [e][d] plain
        K = SEQ; lda = SEQ; ldb = DIM;
    } else {
        Ah = g_qh;  Al = g_ql;       // rows indexed by global m (0..16383)
        A2h = g_ch; A2l = g_cl;
        Bh = g_wh;  Bl = g_wl;
        K = 2 * DIM; lda = DIM; ldb = 2 * DIM;
    }
    const int C = K >> 5;   // chunks of 32

#define LOAD_CHUNK(c, stg)                                                       \
    do {                                                                         \
        const int k0_ = (c) * 32;                                                \
        const bf16 *ah_, *al_; int ka_;                                          \
        if (MODE == 2 && k0_ >= DIM) { ah_ = A2h; al_ = A2l; ka_ = k0_ - DIM; }  \
        else                         { ah_ = Ah;  al_ = Al;  ka_ = k0_; }        \
        const uint32_t sb_ = sm + (stg) * STAGE_B;                               \
        _Pragma("unroll")                                                        \
        for (int i_ = 0; i_ < 2; i_++) {                                         \
            int idx_ = i_ * 256 + tid;                                           \
            int row_ = idx_ >> 2, kc_ = idx_ & 3;                                \
            uint32_t d_ = swz(row_, kc_);                                        \
            const char* pa_ = (const char*)(ah_ + (size_t)(m0 + row_) * lda + ka_) + kc_ * 16; \
            const char* pl_ = (const char*)(al_ + (size_t)(m0 + row_) * lda + ka_) + kc_ * 16; \
            cp16(sb_ + d_, pa_);                                                 \
            cp16(sb_ + TILE_B + d_, pl_);                                        \
        }                                                                        \
        if (MODE == 1) {                                                         \
            /* B tile: 32 e-rows x 256B ([e][d]), xor-swizzled 16B chunks */     \
            _Pragma("unroll")                                                    \
            for (int i_ = 0; i_ < 2; i_++) {                                     \
                int idx_ = i_ * 256 + tid;                                       \
                int row_ = idx_ >> 4, kc_ = idx_ & 15;                           \
                uint32_t d_ = (uint32_t)(row_ * 256 + ((kc_ ^ (row_ & 7)) << 4));\
                const char* pb_ = (const char*)(Bh + (size_t)(k0_ + row_) * ldb + n0) + kc_ * 16; \
                const char* pc_ = (const char*)(Bl + (size_t)(k0_ + row_) * ldb + n0) + kc_ * 16; \
                cp16(sb_ + 2 * TILE_B + d_, pb_);                                \
                cp16(sb_ + 3 * TILE_B + d_, pc_);                                \
            }                                                                    \
        } else {                                                                 \
            _Pragma("unroll")                                                    \
            for (int i_ = 0; i_ < 2; i_++) {                                     \
                int idx_ = i_ * 256 + tid;                                       \
                int row_ = idx_ >> 2, kc_ = idx_ & 3;                            \
                uint32_t d_ = swz(row_, kc_);                                    \
                const char* pb_ = (const char*)(Bh + (size_t)(n0 + row_) * ldb + k0_) + kc_ * 16; \
                const char* pc_ = (const char*)(Bl + (size_t)(n0 + row_) * ldb + k0_) + kc_ * 16; \
                cp16(sb_ + 2 * TILE_B + d_, pb_);                                \
                cp16(sb_ + 3 * TILE_B + d_, pc_);                                \
            }                                                                    \
        }                                                                        \
    } while (0)

    // ---- per-lane ldmatrix address precomputes
    const int ar = lane & 15, ktop = lane >> 4;
    int aoff[2], axr[2];
#pragma unroll
    for (int mi = 0; mi < 2; mi++) {
        int row = wm * 32 + mi * 16 + ar;
        aoff[mi] = row * 64; axr[mi] = (row >> 1) & 3;
    }
    // NT B path (MODE 0/2)
    const int brl = ((lane >> 4) << 3) + (lane & 7);
    const int bk2 = (lane >> 3) & 1;
    int boff[4], bxr[4];
#pragma unroll
    for (int g = 0; g < 4; g++) {
        int nrow = wn * 64 + g * 16 + brl;
        boff[g] = nrow * 64; bxr[g] = (nrow >> 1) & 3;
    }
    // trans B path (MODE 1): mat = lane>>3, rl = lane&7
    const int tmt = lane >> 3, trl = lane & 7;
    const int te_base = ((tmt & 1) << 3) + trl;   // e-row within k16 group
    const int tkc_part = tmt >> 1;                // n8 selector

    float acc[2][8][4];
#pragma unroll
    for (int i = 0; i < 2; i++)
#pragma unroll
        for (int j = 0; j < 8; j++)
#pragma unroll
            for (int q = 0; q < 4; q++) acc[i][j][q] = 0.f;

    LOAD_CHUNK(0, 0); CP_COMMIT();
    LOAD_CHUNK(1, 1); CP_COMMIT();

    for (int c = 0; c < C; c++) {
        CP_WAIT1();
        __syncthreads();
        if (c + 2 < C) { LOAD_CHUNK(c + 2, (c + 2) % NSTAGE); }
        CP_COMMIT();
        const uint32_t sb = sm + (c % NSTAGE) * STAGE_B;
#pragma unroll
        for (int ks = 0; ks < 2; ks++) {
            const int kb = ks * 2;
            uint32_t afr[2][2][4];
#pragma unroll
            for (int mi = 0; mi < 2; mi++)
#pragma unroll
                for (int v = 0; v < 2; v++)
                    ldm4(afr[mi][v],
                         sb + v * TILE_B + aoff[mi] + (((kb + ktop) ^ axr[mi]) << 4));
#pragma unroll
            for (int g = 0; g < 4; g++) {
                uint32_t bh[4], bl[4];
                if (MODE == 1) {
                    const int e_r = ks * 16 + te_base;
                    const int kc = wn * 8 + g * 2 + tkc_part;
                    uint32_t a0 = sb + 2 * TILE_B + e_r * 256 + (((kc ^ trl)) << 4);
                    ldm4t(bh, a0);
                    ldm4t(bl, a0 + TILE_B);
                } else {
                    uint32_t a0 = sb + 2 * TILE_B + boff[g] + (((kb + bk2) ^ bxr[g]) << 4);
                    ldm4(bh, a0);
                    ldm4(bl, a0 + TILE_B);
                }
#pragma unroll
                for (int half = 0; half < 2; half++) {
                    const int nj = g * 2 + half;
                    const int h = half * 2;
#pragma unroll
                    for (int mi = 0; mi < 2; mi++) {
                        mma16816(acc[mi][nj], afr[mi][0], &bh[h]);  // hh
                        mma16816(acc[mi][nj], afr[mi][0], &bl[h]);  // h*l
                        mma16816(acc[mi][nj], afr[mi][1], &bh[h]);  // l*h
                    }
                }
            }
        }
    }
#undef LOAD_CHUNK

    // ---- epilogue from registers
    const int qr = lane >> 2, qc = lane & 3;
#pragma unroll
    for (int mi = 0; mi < 2; mi++)
#pragma unroll
        for (int nj = 0; nj < 8; nj++)
#pragma unroll
            for (int half = 0; half < 2; half++) {
                const int row = m0 + wm * 32 + mi * 16 + qr + half * 8;
                const int col = n0 + wn * 64 + nj * 8 + qc * 2;
                const float v0 = acc[mi][nj][half * 2 + 0];
                const float v1 = acc[mi][nj][half * 2 + 1];
                if (MODE == 0) {
                    float2 o = make_float2(v0 * alpha, v1 * alpha);
                    *(float2*)(Cf + (size_t)b * SEQ * SEQ + (size_t)row * SEQ + col) = o;
                } else if (MODE == 1) {
                    size_t o = (size_t)b * SB + (size_t)row * DIM + col;
                    __nv_bfloat162 H, L;
                    H.x = __float2bfloat16_rn(v0);
                    H.y = __float2bfloat16_rn(v1);
                    L.x = __float2bfloat16_rn(v0 - __bfloat162float(H.x));
                    L.y = __float2bfloat16_rn(v1 - __bfloat162float(H.y));
                    *(__nv_bfloat162*)(g_ch + o) = H;
                    *(__nv_bfloat162*)(g_cl + o) = L;
                } else {
                    const float mk = mask[row];
                    float2 o = make_float2(tanhf(v0 + bias[col]) * mk,
                                           tanhf(v1 + bias[col + 1]) * mk);
                    *(float2*)(Cf + (size_t)row * DIM + col) = o;
                }
            }
}

// ------ fp32 -> bf16 hi/lo split: Q, W, Enc fused in one grid (x4 vec) ------
#define NQ4 (NELEM / 4)
#define NW4 (WELEM / 4)
#define NE4 (NELEM / 4)
__global__ __launch_bounds__(256) void k_split_all(const float4* __restrict__ Qs,
                                                   const float4* __restrict__ Ws,
                                                   const float4* __restrict__ Es)
{
    int i = blockIdx.x * 256 + threadIdx.x;
    const float4* src;
    uint2 *hi, *lo;
    int j;
    if (i < NQ4) { src = Qs; hi = (uint2*)g_qh; lo = (uint2*)g_ql; j = i; }
    else if (i < NQ4 + NW4) { src = Ws; hi = (uint2*)g_wh; lo = (uint2*)g_wl; j = i - NQ4; }
    else if (i < NQ4 + NW4 + NE4) { src = Es; hi = (uint2*)g_eh; lo = (uint2*)g_el; j = i - NQ4 - NW4; }
    else return;
    float4 v = src[j];
    union { bf16 h[4]; uint2 u; } H, L;
    H.h[0] = __float2bfloat16_rn(v.x); L.h[0] = __float2bfloat16_rn(v.x - __bfloat162float(H.h[0]));
    H.h[1] = __float2bfloat16_rn(v.y); L.h[1] = __float2bfloat16_rn(v.y - __bfloat162float(H.h[1]));
    H.h[2] = __float2bfloat16_rn(v.z); L.h[2] = __float2bfloat16_rn(v.z - __bfloat162float(H.h[2]));
    H.h[3] = __float2bfloat16_rn(v.w); L.h[3] = __float2bfloat16_rn(v.w - __bfloat162float(H.h[3]));
    hi[j] = H.u; lo[j] = L.u;
}

// ---------- softmax (in place, float4) + bf16 hi/lo split out ---------------
// 2 rows per block, 128 threads/row, 4 elements/thread.
__global__ __launch_bounds__(256) void k_softmax_split(float* __restrict__ w)
{
    const int g = threadIdx.x >> 7;
    const int r = threadIdx.x & 127;
    const size_t rowid = (size_t)blockIdx.x * 2 + g;
    float4* row = (float4*)(w + rowid * SEQ);
    float4 v = row[r];

    __shared__ float red[2][4];
    const int wl = (threadIdx.x >> 5) & 3;

    float m = fmaxf(fmaxf(v.x, v.y), fmaxf(v.z, v.w));
#pragma unroll
    for (int o = 16; o > 0; o >>= 1) m = fmaxf(m, __shfl_xor_sync(0xffffffffu, m, o));
    if ((threadIdx.x & 31) == 0) red[g][wl] = m;
    __syncthreads();
    const float M = fmaxf(fmaxf(red[g][0], red[g][1]), fmaxf(red[g][2], red[g][3]));
    __syncthreads();

    float4 e;
    e.x = __expf(v.x - M); e.y = __expf(v.y - M);
    e.z = __expf(v.z - M); e.w = __expf(v.w - M);
    float s = e.x + e.y + e.z + e.w;
#pragma unroll
    for (int o = 16; o > 0; o >>= 1) s += __shfl_xor_sync(0xffffffffu, s, o);
    if ((threadIdx.x & 31) == 0) red[g][wl] = s;
    __syncthreads();
    const float S = red[g][0] + red[g][1] + red[g][2] + red[g][3];
    const float inv = 1.0f / S;

    e.x *= inv; e.y *= inv; e.z *= inv; e.w *= inv;
    row[r] = e;

    union { bf16 h[4]; uint2 u; } H, L;
    H.h[0] = __float2bfloat16_rn(e.x); L.h[0] = __float2bfloat16_rn(e.x - __bfloat162float(H.h[0]));
    H.h[1] = __float2bfloat16_rn(e.y); L.h[1] = __float2bfloat16_rn(e.y - __bfloat162float(H.h[1]));
    H.h[2] = __float2bfloat16_rn(e.z); L.h[2] = __float2bfloat16_rn(e.z - __bfloat162float(H.h[2]));
    H.h[3] = __float2bfloat16_rn(e.w); L.h[3] = __float2bfloat16_rn(e.w - __bfloat162float(H.h[3]));
    ((uint2*)(g_awh + rowid * SEQ))[r] = H.u;
    ((uint2*)(g_awl + rowid * SEQ))[r] = L.u;
}

// ---------------------------------------------------------------------------
extern "C" void kernel_launch(void* const* d_in, const int* in_sizes, int n_in,
                              void* d_out, int out_size)
{
    const float* Q    = (const float*)d_in[0];
    const float* Enc  = (const float*)d_in[1];
    const float* mask = (const float*)d_in[2];
    const float* W    = (const float*)d_in[3];
    const float* bias = (const float*)d_in[4];

    float* out_masked  = (float*)d_out;
    float* out_weights = (float*)d_out + NELEM;

    static bool attr_done = false;
    if (!attr_done) {
        cudaFuncSetAttribute(k_gemm<0>, cudaFuncAttributeMaxDynamicSharedMemorySize, SMEM_DYN);
        cudaFuncSetAttribute(k_gemm<1>, cudaFuncAttributeMaxDynamicSharedMemorySize, SMEM_DYN);
        cudaFuncSetAttribute(k_gemm<2>, cudaFuncAttributeMaxDynamicSharedMemorySize, SMEM_DYN);
        attr_done = true;
    }

    const float alpha = 1.0f / sqrtf((float)DIM);

    // 1) one fused split kernel (Q, W, Enc)
    {
        int total = (int)(NQ4 + NW4 + NE4);
        k_split_all<<<(total + 255) / 256, 256>>>((const float4*)Q, (const float4*)W,
                                                  (const float4*)Enc);
    }
    // 2) scores = alpha * Q @ Enc^T -> out_weights (fp32)
    {
        dim3 g(SEQ / 128, SEQ / 128, BATCH);
        k_gemm<0><<<g, 256, SMEM_DYN>>>(out_weights, nullptr, nullptr, alpha);
    }
    // 3) softmax + split
    k_softmax_split<<<BATCH * SEQ / 2, 256>>>(out_weights);
    // 4) ctx = AW @ Enc (trans-B) -> g_ch/g_cl
    {
        dim3 g(DIM / 128, SEQ / 128, BATCH);
        k_gemm<1><<<g, 256, SMEM_DYN>>>(nullptr, nullptr, nullptr, 1.0f);
    }
    // 5) out = tanh([Q|ctx] @ W^T + bias) * mask
    {
        dim3 g(DIM / 128, (BATCH * SEQ) / 128, 1);
        k_gemm<2><<<g, 256, SMEM_DYN>>>(out_masked, bias, mask, 1.0f);
    }
}

// round 8
// speedup vs baseline: 1.6875x; 1.0010x over previous
#include <cuda_runtime.h>
#include <cuda_bf16.h>
#include <cstdint>
#include <math.h>

#define BATCH 32
#define SEQ   512
#define DIM   512

using bf16 = __nv_bfloat16;

// ---------------- scratch (static device memory; no allocations) ------------
#define NELEM ((size_t)BATCH * SEQ * DIM)          // 8,388,608
#define WELEM ((size_t)DIM * 2 * DIM)              // 524,288
__device__ __align__(16) bf16 g_qh[NELEM], g_ql[NELEM];     // Q hi/lo      [b,q,d]
__device__ __align__(16) bf16 g_eh[NELEM], g_el[NELEM];     // Enc hi/lo    [b,e,d]
__device__ __align__(16) bf16 g_awh[NELEM], g_awl[NELEM];   // attn weights [b,q,e]
__device__ __align__(16) bf16 g_ch[NELEM], g_cl[NELEM];     // ctx hi/lo    [b,q,d]
__device__ __align__(16) bf16 g_wh[WELEM], g_wl[WELEM];

// ---------------- PTX helpers (all non-arch-'a'; compile for sm_103) --------
__device__ __forceinline__ uint32_t smem_u32(const void* p) {
    uint32_t a;
    asm("{ .reg .u64 t; cvta.to.shared.u64 t, %1; cvt.u32.u64 %0, t; }" : "=r"(a) : "l"(p));
    return a;
}
__device__ __forceinline__ void cp16(uint32_t dst, const void* src) {
    asm volatile("cp.async.cg.shared.global [%0], [%1], 16;" :: "r"(dst), "l"(src));
}
#define CP_COMMIT() asm volatile("cp.async.commit_group;" ::: "memory")
#define CP_WAIT1()  asm volatile("cp.async.wait_group 1;" ::: "memory")

__device__ __forceinline__ void ldm4(uint32_t* r, uint32_t addr) {
    asm volatile("ldmatrix.sync.aligned.m8n8.x4.shared.b16 {%0,%1,%2,%3}, [%4];"
                 : "=r"(r[0]), "=r"(r[1]), "=r"(r[2]), "=r"(r[3]) : "r"(addr));
}
__device__ __forceinline__ void ldm4t(uint32_t* r, uint32_t addr) {
    asm volatile("ldmatrix.sync.aligned.m8n8.x4.trans.shared.b16 {%0,%1,%2,%3}, [%4];"
                 : "=r"(r[0]), "=r"(r[1]), "=r"(r[2]), "=r"(r[3]) : "r"(addr));
}
__device__ __forceinline__ void mma16816(float* c, const uint32_t* a, const uint32_t* b) {
    asm volatile(
        "mma.sync.aligned.m16n8k16.row.col.f32.bf16.bf16.f32 "
        "{%0,%1,%2,%3}, {%4,%5,%6,%7}, {%8,%9}, {%0,%1,%2,%3};"
        : "+f"(c[0]), "+f"(c[1]), "+f"(c[2]), "+f"(c[3])
        : "r"(a[0]), "r"(a[1]), "r"(a[2]), "r"(a[3]), "r"(b[0]), "r"(b[1]));
}

// ---------------- GEMM: C = A @ B^T, bf16-split (hh + hl + lh) --------------
// CTA tile 128x128, BK=32. 8 warps, warp tile 32(m) x 64(n). 3-stage cp.async.
// MODE 1 feeds B via ldmatrix.trans from plain [e][d] Enc tiles (no EncT).
// Inner loop is TERM-MAJOR: all hh MMAs, then hl, then lh -> accumulator
// reuse distance 4 (was 1) to expose ILP to the tensor pipe.
#define TILE_B   8192
#define STAGE_B  (4 * TILE_B)
#define NSTAGE   3
#define SMEM_DYN (NSTAGE * STAGE_B)
#define SB ((size_t)SEQ * DIM)

// swizzled byte offset within one NT tile for (row, 16B-chunk kc), 64B rows
__device__ __forceinline__ uint32_t swz(int row, int kc) {
    return (uint32_t)(row * 64 + ((kc ^ ((row >> 1) & 3)) << 4));
}

// MODE 0: scores = alpha * Q @ Enc^T          -> Cf (fp32)
// MODE 1: ctx    = AW @ Enc  (trans-B)        -> g_ch/g_cl (bf16 split)
// MODE 2: out    = tanh([Q|ctx] @ W^T + b)*m  -> Cf (fp32)
template <int MODE>
__global__ __launch_bounds__(256, 2) void k_gemm(
    float* __restrict__ Cf, const float* __restrict__ bias,
    const float* __restrict__ mask, float alpha)
{
    extern __shared__ char smem[];
    const uint32_t sm = smem_u32(smem);

    const int tid = threadIdx.x;
    const int lane = tid & 31, wid = tid >> 5;
    const int wm = wid & 3, wn = wid >> 2;       // 4 m-warps x 2 n-warps
    const int b  = blockIdx.z;
    const int m0 = blockIdx.y * 128;
    const int n0 = blockIdx.x * 128;

    const bf16 *Ah, *Al, *A2h = nullptr, *A2l = nullptr, *Bh, *Bl;
    int K, lda, ldb;
    if (MODE == 0) {
        Ah = g_qh + (size_t)b * SB;  Al = g_ql + (size_t)b * SB;
        Bh = g_eh + (size_t)b * SB;  Bl = g_el + (size_t)b * SB;
        K = DIM; lda = DIM; ldb = DIM;
    } else if (MODE == 1) {
        Ah = g_awh + (size_t)b * SB; Al = g_awl + (size_t)b * SB;
        Bh = g_eh + (size_t)b * SB;  Bl = g_el + (size_t)b * SB;   // [e][d] plain
        K = SEQ; lda = SEQ; ldb = DIM;
    } else {
        Ah = g_qh;  Al = g_ql;       // rows indexed by global m (0..16383)
        A2h = g_ch; A2l = g_cl;
        Bh = g_wh;  Bl = g_wl;
        K = 2 * DIM; lda = DIM; ldb = 2 * DIM;
    }
    const int C = K >> 5;   // chunks of 32

#define LOAD_CHUNK(c, stg)                                                       \
    do {                                                                         \
        const int k0_ = (c) * 32;                                                \
        const bf16 *ah_, *al_; int ka_;                                          \
        if (MODE == 2 && k0_ >= DIM) { ah_ = A2h; al_ = A2l; ka_ = k0_ - DIM; }  \
        else                         { ah_ = Ah;  al_ = Al;  ka_ = k0_; }        \
        const uint32_t sb_ = sm + (stg) * STAGE_B;                               \
        _Pragma("unroll")                                                        \
        for (int i_ = 0; i_ < 2; i_++) {                                         \
            int idx_ = i_ * 256 + tid;                                           \
            int row_ = idx_ >> 2, kc_ = idx_ & 3;                                \
            uint32_t d_ = swz(row_, kc_);                                        \
            const char* pa_ = (const char*)(ah_ + (size_t)(m0 + row_) * lda + ka_) + kc_ * 16; \
            const char* pl_ = (const char*)(al_ + (size_t)(m0 + row_) * lda + ka_) + kc_ * 16; \
            cp16(sb_ + d_, pa_);                                                 \
            cp16(sb_ + TILE_B + d_, pl_);                                        \
        }                                                                        \
        if (MODE == 1) {                                                         \
            /* B tile: 32 e-rows x 256B ([e][d]), xor-swizzled 16B chunks */     \
            _Pragma("unroll")                                                    \
            for (int i_ = 0; i_ < 2; i_++) {                                     \
                int idx_ = i_ * 256 + tid;                                       \
                int row_ = idx_ >> 4, kc_ = idx_ & 15;                           \
                uint32_t d_ = (uint32_t)(row_ * 256 + ((kc_ ^ (row_ & 7)) << 4));\
                const char* pb_ = (const char*)(Bh + (size_t)(k0_ + row_) * ldb + n0) + kc_ * 16; \
                const char* pc_ = (const char*)(Bl + (size_t)(k0_ + row_) * ldb + n0) + kc_ * 16; \
                cp16(sb_ + 2 * TILE_B + d_, pb_);                                \
                cp16(sb_ + 3 * TILE_B + d_, pc_);                                \
            }                                                                    \
        } else {                                                                 \
            _Pragma("unroll")                                                    \
            for (int i_ = 0; i_ < 2; i_++) {                                     \
                int idx_ = i_ * 256 + tid;                                       \
                int row_ = idx_ >> 2, kc_ = idx_ & 3;                            \
                uint32_t d_ = swz(row_, kc_);                                    \
                const char* pb_ = (const char*)(Bh + (size_t)(n0 + row_) * ldb + k0_) + kc_ * 16; \
                const char* pc_ = (const char*)(Bl + (size_t)(n0 + row_) * ldb + k0_) + kc_ * 16; \
                cp16(sb_ + 2 * TILE_B + d_, pb_);                                \
                cp16(sb_ + 3 * TILE_B + d_, pc_);                                \
            }                                                                    \
        }                                                                        \
    } while (0)

    // ---- per-lane ldmatrix address precomputes
    const int ar = lane & 15, ktop = lane >> 4;
    int aoff[2], axr[2];
#pragma unroll
    for (int mi = 0; mi < 2; mi++) {
        int row = wm * 32 + mi * 16 + ar;
        aoff[mi] = row * 64; axr[mi] = (row >> 1) & 3;
    }
    // NT B path (MODE 0/2)
    const int brl = ((lane >> 4) << 3) + (lane & 7);
    const int bk2 = (lane >> 3) & 1;
    int boff[4], bxr[4];
#pragma unroll
    for (int g = 0; g < 4; g++) {
        int nrow = wn * 64 + g * 16 + brl;
        boff[g] = nrow * 64; bxr[g] = (nrow >> 1) & 3;
    }
    // trans B path (MODE 1): mat = lane>>3, rl = lane&7
    const int tmt = lane >> 3, trl = lane & 7;
    const int te_base = ((tmt & 1) << 3) + trl;   // e-row within k16 group
    const int tkc_part = tmt >> 1;                // n8 selector

    float acc[2][8][4];
#pragma unroll
    for (int i = 0; i < 2; i++)
#pragma unroll
        for (int j = 0; j < 8; j++)
#pragma unroll
            for (int q = 0; q < 4; q++) acc[i][j][q] = 0.f;

    LOAD_CHUNK(0, 0); CP_COMMIT();
    LOAD_CHUNK(1, 1); CP_COMMIT();

    for (int c = 0; c < C; c++) {
        CP_WAIT1();
        __syncthreads();
        if (c + 2 < C) { LOAD_CHUNK(c + 2, (c + 2) % NSTAGE); }
        CP_COMMIT();
        const uint32_t sb = sm + (c % NSTAGE) * STAGE_B;
#pragma unroll
        for (int ks = 0; ks < 2; ks++) {
            const int kb = ks * 2;
            uint32_t afr[2][2][4];
#pragma unroll
            for (int mi = 0; mi < 2; mi++)
#pragma unroll
                for (int v = 0; v < 2; v++)
                    ldm4(afr[mi][v],
                         sb + v * TILE_B + aoff[mi] + (((kb + ktop) ^ axr[mi]) << 4));
#pragma unroll
            for (int g = 0; g < 4; g++) {
                uint32_t bh[4], bl[4];
                if (MODE == 1) {
                    const int e_r = ks * 16 + te_base;
                    const int kc = wn * 8 + g * 2 + tkc_part;
                    uint32_t a0 = sb + 2 * TILE_B + e_r * 256 + (((kc ^ trl)) << 4);
                    ldm4t(bh, a0);
                    ldm4t(bl, a0 + TILE_B);
                } else {
                    uint32_t a0 = sb + 2 * TILE_B + boff[g] + (((kb + bk2) ^ bxr[g]) << 4);
                    ldm4(bh, a0);
                    ldm4(bl, a0 + TILE_B);
                }
                // TERM-MAJOR: 4 independent MMAs per term before any
                // accumulator is reused (reuse distance 4, was 1).
#pragma unroll
                for (int half = 0; half < 2; half++)     // term hh
#pragma unroll
                    for (int mi = 0; mi < 2; mi++)
                        mma16816(acc[mi][g * 2 + half], afr[mi][0], &bh[half * 2]);
#pragma unroll
                for (int half = 0; half < 2; half++)     // term h*l
#pragma unroll
                    for (int mi = 0; mi < 2; mi++)
                        mma16816(acc[mi][g * 2 + half], afr[mi][0], &bl[half * 2]);
#pragma unroll
                for (int half = 0; half < 2; half++)     // term l*h
#pragma unroll
                    for (int mi = 0; mi < 2; mi++)
                        mma16816(acc[mi][g * 2 + half], afr[mi][1], &bh[half * 2]);
            }
        }
    }
#undef LOAD_CHUNK

    // ---- epilogue from registers
    const int qr = lane >> 2, qc = lane & 3;
#pragma unroll
    for (int mi = 0; mi < 2; mi++)
#pragma unroll
        for (int nj = 0; nj < 8; nj++)
#pragma unroll
            for (int half = 0; half < 2; half++) {
                const int row = m0 + wm * 32 + mi * 16 + qr + half * 8;
                const int col = n0 + wn * 64 + nj * 8 + qc * 2;
                const float v0 = acc[mi][nj][half * 2 + 0];
                const float v1 = acc[mi][nj][half * 2 + 1];
                if (MODE == 0) {
                    float2 o = make_float2(v0 * alpha, v1 * alpha);
                    *(float2*)(Cf + (size_t)b * SEQ * SEQ + (size_t)row * SEQ + col) = o;
                } else if (MODE == 1) {
                    size_t o = (size_t)b * SB + (size_t)row * DIM + col;
                    __nv_bfloat162 H, L;
                    H.x = __float2bfloat16_rn(v0);
                    H.y = __float2bfloat16_rn(v1);
                    L.x = __float2bfloat16_rn(v0 - __bfloat162float(H.x));
                    L.y = __float2bfloat16_rn(v1 - __bfloat162float(H.y));
                    *(__nv_bfloat162*)(g_ch + o) = H;
                    *(__nv_bfloat162*)(g_cl + o) = L;
                } else {
                    const float mk = mask[row];
                    float2 o = make_float2(tanhf(v0 + bias[col]) * mk,
                                           tanhf(v1 + bias[col + 1]) * mk);
                    *(float2*)(Cf + (size_t)row * DIM + col) = o;
                }
            }
}

// ------ fp32 -> bf16 hi/lo split: Q, W, Enc fused in one grid (x4 vec) ------
#define NQ4 (NELEM / 4)
#define NW4 (WELEM / 4)
#define NE4 (NELEM / 4)
__global__ __launch_bounds__(256) void k_split_all(const float4* __restrict__ Qs,
                                                   const float4* __restrict__ Ws,
                                                   const float4* __restrict__ Es)
{
    int i = blockIdx.x * 256 + threadIdx.x;
    const float4* src;
    uint2 *hi, *lo;
    int j;
    if (i < NQ4) { src = Qs; hi = (uint2*)g_qh; lo = (uint2*)g_ql; j = i; }
    else if (i < NQ4 + NW4) { src = Ws; hi = (uint2*)g_wh; lo = (uint2*)g_wl; j = i - NQ4; }
    else if (i < NQ4 + NW4 + NE4) { src = Es; hi = (uint2*)g_eh; lo = (uint2*)g_el; j = i - NQ4 - NW4; }
    else return;
    float4 v = src[j];
    union { bf16 h[4]; uint2 u; } H, L;
    H.h[0] = __float2bfloat16_rn(v.x); L.h[0] = __float2bfloat16_rn(v.x - __bfloat162float(H.h[0]));
    H.h[1] = __float2bfloat16_rn(v.y); L.h[1] = __float2bfloat16_rn(v.y - __bfloat162float(H.h[1]));
    H.h[2] = __float2bfloat16_rn(v.z); L.h[2] = __float2bfloat16_rn(v.z - __bfloat162float(H.h[2]));
    H.h[3] = __float2bfloat16_rn(v.w); L.h[3] = __float2bfloat16_rn(v.w - __bfloat162float(H.h[3]));
    hi[j] = H.u; lo[j] = L.u;
}

// ---------- softmax (in place, float4) + bf16 hi/lo split out ---------------
// 2 rows per block, 128 threads/row, 4 elements/thread.
__global__ __launch_bounds__(256) void k_softmax_split(float* __restrict__ w)
{
    const int g = threadIdx.x >> 7;
    const int r = threadIdx.x & 127;
    const size_t rowid = (size_t)blockIdx.x * 2 + g;
    float4* row = (float4*)(w + rowid * SEQ);
    float4 v = row[r];

    __shared__ float red[2][4];
    const int wl = (threadIdx.x >> 5) & 3;

    float m = fmaxf(fmaxf(v.x, v.y), fmaxf(v.z, v.w));
#pragma unroll
    for (int o = 16; o > 0; o >>= 1) m = fmaxf(m, __shfl_xor_sync(0xffffffffu, m, o));
    if ((threadIdx.x & 31) == 0) red[g][wl] = m;
    __syncthreads();
    const float M = fmaxf(fmaxf(red[g][0], red[g][1]), fmaxf(red[g][2], red[g][3]));
    __syncthreads();

    float4 e;
    e.x = __expf(v.x - M); e.y = __expf(v.y - M);
    e.z = __expf(v.z - M); e.w = __expf(v.w - M);
    float s = e.x + e.y + e.z + e.w;
#pragma unroll
    for (int o = 16; o > 0; o >>= 1) s += __shfl_xor_sync(0xffffffffu, s, o);
    if ((threadIdx.x & 31) == 0) red[g][wl] = s;
    __syncthreads();
    const float S = red[g][0] + red[g][1] + red[g][2] + red[g][3];
    const float inv = 1.0f / S;

    e.x *= inv; e.y *= inv; e.z *= inv; e.w *= inv;
    row[r] = e;

    union { bf16 h[4]; uint2 u; } H, L;
    H.h[0] = __float2bfloat16_rn(e.x); L.h[0] = __float2bfloat16_rn(e.x - __bfloat162float(H.h[0]));
    H.h[1] = __float2bfloat16_rn(e.y); L.h[1] = __float2bfloat16_rn(e.y - __bfloat162float(H.h[1]));
    H.h[2] = __float2bfloat16_rn(e.z); L.h[2] = __float2bfloat16_rn(e.z - __bfloat162float(H.h[2]));
    H.h[3] = __float2bfloat16_rn(e.w); L.h[3] = __float2bfloat16_rn(e.w - __bfloat162float(H.h[3]));
    ((uint2*)(g_awh + rowid * SEQ))[r] = H.u;
    ((uint2*)(g_awl + rowid * SEQ))[r] = L.u;
}

// ---------------------------------------------------------------------------
extern "C" void kernel_launch(void* const* d_in, const int* in_sizes, int n_in,
                              void* d_out, int out_size)
{
    const float* Q    = (const float*)d_in[0];
    const float* Enc  = (const float*)d_in[1];
    const float* mask = (const float*)d_in[2];
    const float* W    = (const float*)d_in[3];
    const float* bias = (const float*)d_in[4];

    float* out_masked  = (float*)d_out;
    float* out_weights = (float*)d_out + NELEM;

    static bool attr_done = false;
    if (!attr_done) {
        cudaFuncSetAttribute(k_gemm<0>, cudaFuncAttributeMaxDynamicSharedMemorySize, SMEM_DYN);
        cudaFuncSetAttribute(k_gemm<1>, cudaFuncAttributeMaxDynamicSharedMemorySize, SMEM_DYN);
        cudaFuncSetAttribute(k_gemm<2>, cudaFuncAttributeMaxDynamicSharedMemorySize, SMEM_DYN);
        attr_done = true;
    }

    const float alpha = 1.0f / sqrtf((float)DIM);

    // 1) one fused split kernel (Q, W, Enc)
    {
        int total = (int)(NQ4 + NW4 + NE4);
        k_split_all<<<(total + 255) / 256, 256>>>((const float4*)Q, (const float4*)W,
                                                  (const float4*)Enc);
    }
    // 2) scores = alpha * Q @ Enc^T -> out_weights (fp32)
    {
        dim3 g(SEQ / 128, SEQ / 128, BATCH);
        k_gemm<0><<<g, 256, SMEM_DYN>>>(out_weights, nullptr, nullptr, alpha);
    }
    // 3) softmax + split
    k_softmax_split<<<BATCH * SEQ / 2, 256>>>(out_weights);
    // 4) ctx = AW @ Enc (trans-B) -> g_ch/g_cl
    {
        dim3 g(DIM / 128, SEQ / 128, BATCH);
        k_gemm<1><<<g, 256, SMEM_DYN>>>(nullptr, nullptr, nullptr, 1.0f);
    }
    // 5) out = tanh([Q|ctx] @ W^T + bias) * mask
    {
        dim3 g(DIM / 128, (BATCH * SEQ) / 128, 1);
        k_gemm<2><<<g, 256, SMEM_DYN>>>(out_masked, bias, mask, 1.0f);
    }
}

// round 9
// speedup vs baseline: 1.8369x; 1.0885x over previous
#include <cuda_runtime.h>
#include <cuda_bf16.h>
#include <cstdint>
#include <math.h>

#define BATCH 32
#define SEQ   512
#define DIM   512

using bf16 = __nv_bfloat16;

// ---------------- scratch (static device memory; no allocations) ------------
#define NELEM ((size_t)BATCH * SEQ * DIM)          // 8,388,608
#define WELEM ((size_t)DIM * 2 * DIM)              // 524,288
__device__ __align__(16) bf16 g_qh[NELEM], g_ql[NELEM];     // Q hi/lo      [b,q,d]
__device__ __align__(16) bf16 g_eh[NELEM], g_el[NELEM];     // Enc hi/lo    [b,e,d]
__device__ __align__(16) bf16 g_awh[NELEM], g_awl[NELEM];   // attn weights [b,q,e]
__device__ __align__(16) bf16 g_ch[NELEM], g_cl[NELEM];     // ctx hi/lo    [b,q,d]
__device__ __align__(16) bf16 g_wh[WELEM], g_wl[WELEM];

// ---------------- PTX helpers (all non-arch-'a'; compile for sm_103) --------
__device__ __forceinline__ uint32_t smem_u32(const void* p) {
    uint32_t a;
    asm("{ .reg .u64 t; cvta.to.shared.u64 t, %1; cvt.u32.u64 %0, t; }" : "=r"(a) : "l"(p));
    return a;
}
__device__ __forceinline__ void cp16(uint32_t dst, const void* src) {
    asm volatile("cp.async.cg.shared.global [%0], [%1], 16;" :: "r"(dst), "l"(src));
}
#define CP_COMMIT() asm volatile("cp.async.commit_group;" ::: "memory")
#define CP_WAIT1()  asm volatile("cp.async.wait_group 1;" ::: "memory")

__device__ __forceinline__ void ldm4(uint32_t* r, uint32_t addr) {
    asm volatile("ldmatrix.sync.aligned.m8n8.x4.shared.b16 {%0,%1,%2,%3}, [%4];"
                 : "=r"(r[0]), "=r"(r[1]), "=r"(r[2]), "=r"(r[3]) : "r"(addr));
}
__device__ __forceinline__ void ldm4t(uint32_t* r, uint32_t addr) {
    asm volatile("ldmatrix.sync.aligned.m8n8.x4.trans.shared.b16 {%0,%1,%2,%3}, [%4];"
                 : "=r"(r[0]), "=r"(r[1]), "=r"(r[2]), "=r"(r[3]) : "r"(addr));
}
__device__ __forceinline__ void mma16816(float* c, const uint32_t* a, const uint32_t* b) {
    asm volatile(
        "mma.sync.aligned.m16n8k16.row.col.f32.bf16.bf16.f32 "
        "{%0,%1,%2,%3}, {%4,%5,%6,%7}, {%8,%9}, {%0,%1,%2,%3};"
        : "+f"(c[0]), "+f"(c[1]), "+f"(c[2]), "+f"(c[3])
        : "r"(a[0]), "r"(a[1]), "r"(a[2]), "r"(a[3]), "r"(b[0]), "r"(b[1]));
}

// ---------------- GEMM: C = A @ B^T, bf16-split (hh + hl + lh) --------------
// CTA tile 128(m) x 64(n), BK=32. 8 warps = 4m x 2n, warp tile 32x32.
// smem/stage: A hi+lo 16KB, B hi+lo 8KB = 24KB; 3 stages = 72KB.
// launch_bounds(256,3): cap regs ~85 -> 3 CTAs/SM = 24 warps (216KB smem).
#define TILE_A   8192           // 128 rows x 64B
#define TILE_BB  4096           // 64 rows x 64B (or 32 rows x 128B for MODE1)
#define STAGE_B  (2 * TILE_A + 2 * TILE_BB)   // 24576
#define OFF_AL   TILE_A
#define OFF_BH   (2 * TILE_A)
#define OFF_BL   (2 * TILE_A + TILE_BB)
#define NSTAGE   3
#define SMEM_DYN (NSTAGE * STAGE_B)
#define SB ((size_t)SEQ * DIM)

// swizzled byte offset within one NT tile for (row, 16B-chunk kc), 64B rows
__device__ __forceinline__ uint32_t swz(int row, int kc) {
    return (uint32_t)(row * 64 + ((kc ^ ((row >> 1) & 3)) << 4));
}

// MODE 0: scores = alpha * Q @ Enc^T          -> Cf (fp32)
// MODE 1: ctx    = AW @ Enc  (trans-B)        -> g_ch/g_cl (bf16 split)
// MODE 2: out    = tanh([Q|ctx] @ W^T + b)*m  -> Cf (fp32)
template <int MODE>
__global__ __launch_bounds__(256, 3) void k_gemm(
    float* __restrict__ Cf, const float* __restrict__ bias,
    const float* __restrict__ mask, float alpha)
{
    extern __shared__ char smem[];
    const uint32_t sm = smem_u32(smem);

    const int tid = threadIdx.x;
    const int lane = tid & 31, wid = tid >> 5;
    const int wm = wid & 3, wn = wid >> 2;       // 4 m-warps x 2 n-warps
    const int b  = blockIdx.z;
    const int m0 = blockIdx.y * 128;
    const int n0 = blockIdx.x * 64;

    const bf16 *Ah, *Al, *A2h = nullptr, *A2l = nullptr, *Bh, *Bl;
    int K, lda, ldb;
    if (MODE == 0) {
        Ah = g_qh + (size_t)b * SB;  Al = g_ql + (size_t)b * SB;
        Bh = g_eh + (size_t)b * SB;  Bl = g_el + (size_t)b * SB;
        K = DIM; lda = DIM; ldb = DIM;
    } else if (MODE == 1) {
        Ah = g_awh + (size_t)b * SB; Al = g_awl + (size_t)b * SB;
        Bh = g_eh + (size_t)b * SB;  Bl = g_el + (size_t)b * SB;   // [e][d] plain
        K = SEQ; lda = SEQ; ldb = DIM;
    } else {
        Ah = g_qh;  Al = g_ql;       // rows indexed by global m (0..16383)
        A2h = g_ch; A2l = g_cl;
        Bh = g_wh;  Bl = g_wl;
        K = 2 * DIM; lda = DIM; ldb = 2 * DIM;
    }
    const int C = K >> 5;   // chunks of 32

#define LOAD_CHUNK(c, stg)                                                       \
    do {                                                                         \
        const int k0_ = (c) * 32;                                                \
        const bf16 *ah_, *al_; int ka_;                                          \
        if (MODE == 2 && k0_ >= DIM) { ah_ = A2h; al_ = A2l; ka_ = k0_ - DIM; }  \
        else                         { ah_ = Ah;  al_ = Al;  ka_ = k0_; }        \
        const uint32_t sb_ = sm + (stg) * STAGE_B;                               \
        _Pragma("unroll")                                                        \
        for (int i_ = 0; i_ < 2; i_++) {  /* A: 128 rows x 4 kc = 512 chunks */  \
            int idx_ = i_ * 256 + tid;                                           \
            int row_ = idx_ >> 2, kc_ = idx_ & 3;                                \
            uint32_t d_ = swz(row_, kc_);                                        \
            const char* pa_ = (const char*)(ah_ + (size_t)(m0 + row_) * lda + ka_) + kc_ * 16; \
            const char* pl_ = (const char*)(al_ + (size_t)(m0 + row_) * lda + ka_) + kc_ * 16; \
            cp16(sb_ + d_, pa_);                                                 \
            cp16(sb_ + OFF_AL + d_, pl_);                                        \
        }                                                                        \
        if (MODE == 1) {                                                         \
            /* B tile: 32 e-rows x 128B ([e][d] slice), 256 chunks */            \
            int row_ = tid >> 3, kc_ = tid & 7;                                  \
            uint32_t d_ = (uint32_t)(row_ * 128 + ((kc_ ^ (row_ & 7)) << 4));    \
            const char* pb_ = (const char*)(Bh + (size_t)(k0_ + row_) * ldb + n0) + kc_ * 16; \
            const char* pc_ = (const char*)(Bl + (size_t)(k0_ + row_) * ldb + n0) + kc_ * 16; \
            cp16(sb_ + OFF_BH + d_, pb_);                                        \
            cp16(sb_ + OFF_BL + d_, pc_);                                        \
        } else {                                                                 \
            /* B tile: 64 n-rows x 4 kc = 256 chunks */                          \
            int row_ = tid >> 2, kc_ = tid & 3;                                  \
            uint32_t d_ = swz(row_, kc_);                                        \
            const char* pb_ = (const char*)(Bh + (size_t)(n0 + row_) * ldb + k0_) + kc_ * 16; \
            const char* pc_ = (const char*)(Bl + (size_t)(n0 + row_) * ldb + k0_) + kc_ * 16; \
            cp16(sb_ + OFF_BH + d_, pb_);                                        \
            cp16(sb_ + OFF_BL + d_, pc_);                                        \
        }                                                                        \
    } while (0)

    // ---- per-lane ldmatrix address precomputes
    const int ar = lane & 15, ktop = lane >> 4;
    int aoff[2], axr[2];
#pragma unroll
    for (int mi = 0; mi < 2; mi++) {
        int row = wm * 32 + mi * 16 + ar;
        aoff[mi] = row * 64; axr[mi] = (row >> 1) & 3;
    }
    // NT B path (MODE 0/2): 2 groups of 16 n-rows per warp
    const int brl = ((lane >> 4) << 3) + (lane & 7);
    const int bk2 = (lane >> 3) & 1;
    int boff[2], bxr[2];
#pragma unroll
    for (int g = 0; g < 2; g++) {
        int nrow = wn * 32 + g * 16 + brl;
        boff[g] = nrow * 64; bxr[g] = (nrow >> 1) & 3;
    }
    // trans B path (MODE 1): mat = lane>>3, rl = lane&7
    const int tmt = lane >> 3, trl = lane & 7;
    const int te_base = ((tmt & 1) << 3) + trl;   // e-row within k16 group
    const int tkc_part = tmt >> 1;                // n8 selector

    float acc[2][4][4];
#pragma unroll
    for (int i = 0; i < 2; i++)
#pragma unroll
        for (int j = 0; j < 4; j++)
#pragma unroll
            for (int q = 0; q < 4; q++) acc[i][j][q] = 0.f;

    LOAD_CHUNK(0, 0); CP_COMMIT();
    LOAD_CHUNK(1, 1); CP_COMMIT();

    for (int c = 0; c < C; c++) {
        CP_WAIT1();
        __syncthreads();
        if (c + 2 < C) { LOAD_CHUNK(c + 2, (c + 2) % NSTAGE); }
        CP_COMMIT();
        const uint32_t sb = sm + (c % NSTAGE) * STAGE_B;
#pragma unroll
        for (int ks = 0; ks < 2; ks++) {
            const int kb = ks * 2;
            uint32_t afr[2][2][4];
#pragma unroll
            for (int mi = 0; mi < 2; mi++)
#pragma unroll
                for (int v = 0; v < 2; v++)
                    ldm4(afr[mi][v],
                         sb + v * OFF_AL + aoff[mi] + (((kb + ktop) ^ axr[mi]) << 4));
#pragma unroll
            for (int g = 0; g < 2; g++) {
                uint32_t bh[4], bl[4];
                if (MODE == 1) {
                    const int e_r = ks * 16 + te_base;
                    const int kc = wn * 4 + g * 2 + tkc_part;
                    uint32_t a0 = sb + OFF_BH + e_r * 128 + ((kc ^ trl) << 4);
                    ldm4t(bh, a0);
                    ldm4t(bl, a0 + TILE_BB);
                } else {
                    uint32_t a0 = sb + OFF_BH + boff[g] + (((kb + bk2) ^ bxr[g]) << 4);
                    ldm4(bh, a0);
                    ldm4(bl, a0 + TILE_BB);
                }
#pragma unroll
                for (int half = 0; half < 2; half++)     // term hh
#pragma unroll
                    for (int mi = 0; mi < 2; mi++)
                        mma16816(acc[mi][g * 2 + half], afr[mi][0], &bh[half * 2]);
#pragma unroll
                for (int half = 0; half < 2; half++)     // term h*l
#pragma unroll
                    for (int mi = 0; mi < 2; mi++)
                        mma16816(acc[mi][g * 2 + half], afr[mi][0], &bl[half * 2]);
#pragma unroll
                for (int half = 0; half < 2; half++)     // term l*h
#pragma unroll
                    for (int mi = 0; mi < 2; mi++)
                        mma16816(acc[mi][g * 2 + half], afr[mi][1], &bh[half * 2]);
            }
        }
    }
#undef LOAD_CHUNK

    // ---- epilogue from registers
    const int qr = lane >> 2, qc = lane & 3;
#pragma unroll
    for (int mi = 0; mi < 2; mi++)
#pragma unroll
        for (int nj = 0; nj < 4; nj++)
#pragma unroll
            for (int half = 0; half < 2; half++) {
                const int row = m0 + wm * 32 + mi * 16 + qr + half * 8;
                const int col = n0 + wn * 32 + nj * 8 + qc * 2;
                const float v0 = acc[mi][nj][half * 2 + 0];
                const float v1 = acc[mi][nj][half * 2 + 1];
                if (MODE == 0) {
                    float2 o = make_float2(v0 * alpha, v1 * alpha);
                    *(float2*)(Cf + (size_t)b * SEQ * SEQ + (size_t)row * SEQ + col) = o;
                } else if (MODE == 1) {
                    size_t o = (size_t)b * SB + (size_t)row * DIM + col;
                    __nv_bfloat162 H, L;
                    H.x = __float2bfloat16_rn(v0);
                    H.y = __float2bfloat16_rn(v1);
                    L.x = __float2bfloat16_rn(v0 - __bfloat162float(H.x));
                    L.y = __float2bfloat16_rn(v1 - __bfloat162float(H.y));
                    *(__nv_bfloat162*)(g_ch + o) = H;
                    *(__nv_bfloat162*)(g_cl + o) = L;
                } else {
                    const float mk = mask[row];
                    float2 o = make_float2(tanhf(v0 + bias[col]) * mk,
                                           tanhf(v1 + bias[col + 1]) * mk);
                    *(float2*)(Cf + (size_t)row * DIM + col) = o;
                }
            }
}

// ------ fp32 -> bf16 hi/lo split: Q, W, Enc fused in one grid (x4 vec) ------
#define NQ4 (NELEM / 4)
#define NW4 (WELEM / 4)
#define NE4 (NELEM / 4)
__global__ __launch_bounds__(256) void k_split_all(const float4* __restrict__ Qs,
                                                   const float4* __restrict__ Ws,
                                                   const float4* __restrict__ Es)
{
    int i = blockIdx.x * 256 + threadIdx.x;
    const float4* src;
    uint2 *hi, *lo;
    int j;
    if (i < NQ4) { src = Qs; hi = (uint2*)g_qh; lo = (uint2*)g_ql; j = i; }
    else if (i < NQ4 + NW4) { src = Ws; hi = (uint2*)g_wh; lo = (uint2*)g_wl; j = i - NQ4; }
    else if (i < NQ4 + NW4 + NE4) { src = Es; hi = (uint2*)g_eh; lo = (uint2*)g_el; j = i - NQ4 - NW4; }
    else return;
    float4 v = src[j];
    union { bf16 h[4]; uint2 u; } H, L;
    H.h[0] = __float2bfloat16_rn(v.x); L.h[0] = __float2bfloat16_rn(v.x - __bfloat162float(H.h[0]));
    H.h[1] = __float2bfloat16_rn(v.y); L.h[1] = __float2bfloat16_rn(v.y - __bfloat162float(H.h[1]));
    H.h[2] = __float2bfloat16_rn(v.z); L.h[2] = __float2bfloat16_rn(v.z - __bfloat162float(H.h[2]));
    H.h[3] = __float2bfloat16_rn(v.w); L.h[3] = __float2bfloat16_rn(v.w - __bfloat162float(H.h[3]));
    hi[j] = H.u; lo[j] = L.u;
}

// ---------- softmax (in place, float4) + bf16 hi/lo split out ---------------
// 2 rows per block, 128 threads/row, 4 elements/thread.
__global__ __launch_bounds__(256) void k_softmax_split(float* __restrict__ w)
{
    const int g = threadIdx.x >> 7;
    const int r = threadIdx.x & 127;
    const size_t rowid = (size_t)blockIdx.x * 2 + g;
    float4* row = (float4*)(w + rowid * SEQ);
    float4 v = row[r];

    __shared__ float red[2][4];
    const int wl = (threadIdx.x >> 5) & 3;

    float m = fmaxf(fmaxf(v.x, v.y), fmaxf(v.z, v.w));
#pragma unroll
    for (int o = 16; o > 0; o >>= 1) m = fmaxf(m, __shfl_xor_sync(0xffffffffu, m, o));
    if ((threadIdx.x & 31) == 0) red[g][wl] = m;
    __syncthreads();
    const float M = fmaxf(fmaxf(red[g][0], red[g][1]), fmaxf(red[g][2], red[g][3]));
    __syncthreads();

    float4 e;
    e.x = __expf(v.x - M); e.y = __expf(v.y - M);
    e.z = __expf(v.z - M); e.w = __expf(v.w - M);
    float s = e.x + e.y + e.z + e.w;
#pragma unroll
    for (int o = 16; o > 0; o >>= 1) s += __shfl_xor_sync(0xffffffffu, s, o);
    if ((threadIdx.x & 31) == 0) red[g][wl] = s;
    __syncthreads();
    const float S = red[g][0] + red[g][1] + red[g][2] + red[g][3];
    const float inv = 1.0f / S;

    e.x *= inv; e.y *= inv; e.z *= inv; e.w *= inv;
    row[r] = e;

    union { bf16 h[4]; uint2 u; } H, L;
    H.h[0] = __float2bfloat16_rn(e.x); L.h[0] = __float2bfloat16_rn(e.x - __bfloat162float(H.h[0]));
    H.h[1] = __float2bfloat16_rn(e.y); L.h[1] = __float2bfloat16_rn(e.y - __bfloat162float(H.h[1]));
    H.h[2] = __float2bfloat16_rn(e.z); L.h[2] = __float2bfloat16_rn(e.z - __bfloat162float(H.h[2]));
    H.h[3] = __float2bfloat16_rn(e.w); L.h[3] = __float2bfloat16_rn(e.w - __bfloat162float(H.h[3]));
    ((uint2*)(g_awh + rowid * SEQ))[r] = H.u;
    ((uint2*)(g_awl + rowid * SEQ))[r] = L.u;
}

// ---------------------------------------------------------------------------
extern "C" void kernel_launch(void* const* d_in, const int* in_sizes, int n_in,
                              void* d_out, int out_size)
{
    const float* Q    = (const float*)d_in[0];
    const float* Enc  = (const float*)d_in[1];
    const float* mask = (const float*)d_in[2];
    const float* W    = (const float*)d_in[3];
    const float* bias = (const float*)d_in[4];

    float* out_masked  = (float*)d_out;
    float* out_weights = (float*)d_out + NELEM;

    static bool attr_done = false;
    if (!attr_done) {
        cudaFuncSetAttribute(k_gemm<0>, cudaFuncAttributeMaxDynamicSharedMemorySize, SMEM_DYN);
        cudaFuncSetAttribute(k_gemm<1>, cudaFuncAttributeMaxDynamicSharedMemorySize, SMEM_DYN);
        cudaFuncSetAttribute(k_gemm<2>, cudaFuncAttributeMaxDynamicSharedMemorySize, SMEM_DYN);
        attr_done = true;
    }

    const float alpha = 1.0f / sqrtf((float)DIM);

    // 1) one fused split kernel (Q, W, Enc)
    {
        int total = (int)(NQ4 + NW4 + NE4);
        k_split_all<<<(total + 255) / 256, 256>>>((const float4*)Q, (const float4*)W,
                                                  (const float4*)Enc);
    }
    // 2) scores = alpha * Q @ Enc^T -> out_weights (fp32)
    {
        dim3 g(SEQ / 64, SEQ / 128, BATCH);
        k_gemm<0><<<g, 256, SMEM_DYN>>>(out_weights, nullptr, nullptr, alpha);
    }
    // 3) softmax + split
    k_softmax_split<<<BATCH * SEQ / 2, 256>>>(out_weights);
    // 4) ctx = AW @ Enc (trans-B) -> g_ch/g_cl
    {
        dim3 g(DIM / 64, SEQ / 128, BATCH);
        k_gemm<1><<<g, 256, SMEM_DYN>>>(nullptr, nullptr, nullptr, 1.0f);
    }
    // 5) out = tanh([Q|ctx] @ W^T + bias) * mask
    {
        dim3 g(DIM / 64, (BATCH * SEQ) / 128, 1);
        k_gemm<2><<<g, 256, SMEM_DYN>>>(out_masked, bias, mask, 1.0f);
    }
}

// round 10
// speedup vs baseline: 2.3829x; 1.2973x over previous
#include <cuda_runtime.h>
#include <cuda_fp16.h>
#include <cstdint>
#include <math.h>

#define BATCH 32
#define SEQ   512
#define DIM   512

// ---------------- scratch (static device memory; no allocations) ------------
#define NELEM ((size_t)BATCH * SEQ * DIM)          // 8,388,608
#define WELEM ((size_t)DIM * 2 * DIM)              // 524,288
__device__ __align__(16) __half g_qh[NELEM], g_ql[NELEM];   // Q hi/lo      [b,q,d]
__device__ __align__(16) __half g_eh[NELEM], g_el[NELEM];   // Enc hi/lo    [b,e,d]
__device__ __align__(16) __half g_awh[NELEM];               // attn weights [b,q,e] (hi only)
__device__ __align__(16) __half g_ch[NELEM];                // ctx hi       [b,q,d]
__device__ __align__(16) __half g_wh[WELEM], g_wl[WELEM];   // W hi/lo

// ---------------- PTX helpers (all non-arch-'a'; compile for sm_103) --------
__device__ __forceinline__ uint32_t smem_u32(const void* p) {
    uint32_t a;
    asm("{ .reg .u64 t; cvta.to.shared.u64 t, %1; cvt.u32.u64 %0, t; }" : "=r"(a) : "l"(p));
    return a;
}
__device__ __forceinline__ void cp16(uint32_t dst, const void* src) {
    asm volatile("cp.async.cg.shared.global [%0], [%1], 16;" :: "r"(dst), "l"(src));
}
#define CP_COMMIT() asm volatile("cp.async.commit_group;" ::: "memory")
#define CP_WAIT1()  asm volatile("cp.async.wait_group 1;" ::: "memory")

__device__ __forceinline__ void ldm4(uint32_t* r, uint32_t addr) {
    asm volatile("ldmatrix.sync.aligned.m8n8.x4.shared.b16 {%0,%1,%2,%3}, [%4];"
                 : "=r"(r[0]), "=r"(r[1]), "=r"(r[2]), "=r"(r[3]) : "r"(addr));
}
__device__ __forceinline__ void ldm4t(uint32_t* r, uint32_t addr) {
    asm volatile("ldmatrix.sync.aligned.m8n8.x4.trans.shared.b16 {%0,%1,%2,%3}, [%4];"
                 : "=r"(r[0]), "=r"(r[1]), "=r"(r[2]), "=r"(r[3]) : "r"(addr));
}
__device__ __forceinline__ void mma16816(float* c, const uint32_t* a, const uint32_t* b) {
    asm volatile(
        "mma.sync.aligned.m16n8k16.row.col.f32.f16.f16.f32 "
        "{%0,%1,%2,%3}, {%4,%5,%6,%7}, {%8,%9}, {%0,%1,%2,%3};"
        : "+f"(c[0]), "+f"(c[1]), "+f"(c[2]), "+f"(c[3])
        : "r"(a[0]), "r"(a[1]), "r"(a[2]), "r"(a[3]), "r"(b[0]), "r"(b[1]));
}

// ---------------- GEMM: C = A @ B^T, fp16-split -----------------------------
// CTA tile 128(m) x 64(n), BK=32. 8 warps = 4m x 2n, warp tile 32x32.
// MODE 0: 3-term (AhBh + AhBl + AlBh), A hi+lo in smem. stage 24KB.
// MODE 1/2: 2-term (AhBh + AhBl), A hi only. stage 16KB.
#define TILE_A   8192           // 128 rows x 64B
#define TILE_BB  4096           // 64 rows x 64B (or 32 rows x 128B for MODE1)
#define NSTAGE   3
#define SB ((size_t)SEQ * DIM)

// swizzled byte offset within one NT tile for (row, 16B-chunk kc), 64B rows
__device__ __forceinline__ uint32_t swz(int row, int kc) {
    return (uint32_t)(row * 64 + ((kc ^ ((row >> 1) & 3)) << 4));
}

// MODE 0: scores = alpha * Q @ Enc^T          -> Cf (fp32)      [3-term]
// MODE 1: ctx    = AW @ Enc  (trans-B)        -> g_ch (fp16 hi) [2-term]
// MODE 2: out    = tanh([Q|ctx] @ W^T + b)*m  -> Cf (fp32)      [2-term]
template <int MODE>
__global__ __launch_bounds__(256, 3) void k_gemm(
    float* __restrict__ Cf, const float* __restrict__ bias,
    const float* __restrict__ mask, float alpha)
{
    constexpr int OFFAL  = TILE_A;                              // A-lo (MODE0 only)
    constexpr int OFFBH  = (MODE == 0) ? 2 * TILE_A : TILE_A;
    constexpr int OFFBL  = OFFBH + TILE_BB;
    constexpr int STAGEB = OFFBL + TILE_BB;                     // 24KB or 16KB

    extern __shared__ char smem[];
    const uint32_t sm = smem_u32(smem);

    const int tid = threadIdx.x;
    const int lane = tid & 31, wid = tid >> 5;
    const int wm = wid & 3, wn = wid >> 2;       // 4 m-warps x 2 n-warps
    const int b  = blockIdx.z;
    const int m0 = blockIdx.y * 128;
    const int n0 = blockIdx.x * 64;

    const __half *Ah, *Al = nullptr, *A2h = nullptr, *Bh, *Bl;
    int K, lda, ldb;
    if (MODE == 0) {
        Ah = g_qh + (size_t)b * SB;  Al = g_ql + (size_t)b * SB;
        Bh = g_eh + (size_t)b * SB;  Bl = g_el + (size_t)b * SB;
        K = DIM; lda = DIM; ldb = DIM;
    } else if (MODE == 1) {
        Ah = g_awh + (size_t)b * SB;
        Bh = g_eh + (size_t)b * SB;  Bl = g_el + (size_t)b * SB;   // [e][d] plain
        K = SEQ; lda = SEQ; ldb = DIM;
    } else {
        Ah = g_qh;  A2h = g_ch;      // rows indexed by global m (0..16383)
        Bh = g_wh;  Bl = g_wl;
        K = 2 * DIM; lda = DIM; ldb = 2 * DIM;
    }
    const int C = K >> 5;   // chunks of 32

#define LOAD_CHUNK(c, stg)                                                       \
    do {                                                                         \
        const int k0_ = (c) * 32;                                                \
        const __half* ah_; int ka_;                                              \
        if (MODE == 2 && k0_ >= DIM) { ah_ = A2h; ka_ = k0_ - DIM; }             \
        else                         { ah_ = Ah;  ka_ = k0_; }                   \
        const uint32_t sb_ = sm + (stg) * STAGEB;                                \
        _Pragma("unroll")                                                        \
        for (int i_ = 0; i_ < 2; i_++) {  /* A hi: 128 rows x 4 kc = 512 */      \
            int idx_ = i_ * 256 + tid;                                           \
            int row_ = idx_ >> 2, kc_ = idx_ & 3;                                \
            uint32_t d_ = swz(row_, kc_);                                        \
            cp16(sb_ + d_, (const char*)(ah_ + (size_t)(m0 + row_) * lda + ka_) + kc_ * 16); \
            if (MODE == 0)                                                       \
                cp16(sb_ + OFFAL + d_, (const char*)(Al + (size_t)(m0 + row_) * lda + ka_) + kc_ * 16); \
        }                                                                        \
        if (MODE == 1) {                                                         \
            /* B tile: 32 e-rows x 128B ([e][d] slice), 256 chunks */            \
            int row_ = tid >> 3, kc_ = tid & 7;                                  \
            uint32_t d_ = (uint32_t)(row_ * 128 + ((kc_ ^ (row_ & 7)) << 4));    \
            cp16(sb_ + OFFBH + d_, (const char*)(Bh + (size_t)(k0_ + row_) * ldb + n0) + kc_ * 16); \
            cp16(sb_ + OFFBL + d_, (const char*)(Bl + (size_t)(k0_ + row_) * ldb + n0) + kc_ * 16); \
        } else {                                                                 \
            /* B tile: 64 n-rows x 4 kc = 256 chunks */                          \
            int row_ = tid >> 2, kc_ = tid & 3;                                  \
            uint32_t d_ = swz(row_, kc_);                                        \
            cp16(sb_ + OFFBH + d_, (const char*)(Bh + (size_t)(n0 + row_) * ldb + k0_) + kc_ * 16); \
            cp16(sb_ + OFFBL + d_, (const char*)(Bl + (size_t)(n0 + row_) * ldb + k0_) + kc_ * 16); \
        }                                                                        \
    } while (0)

    // ---- per-lane ldmatrix address precomputes
    const int ar = lane & 15, ktop = lane >> 4;
    int aoff[2], axr[2];
#pragma unroll
    for (int mi = 0; mi < 2; mi++) {
        int row = wm * 32 + mi * 16 + ar;
        aoff[mi] = row * 64; axr[mi] = (row >> 1) & 3;
    }
    // NT B path (MODE 0/2): 2 groups of 16 n-rows per warp
    const int brl = ((lane >> 4) << 3) + (lane & 7);
    const int bk2 = (lane >> 3) & 1;
    int boff[2], bxr[2];
#pragma unroll
    for (int g = 0; g < 2; g++) {
        int nrow = wn * 32 + g * 16 + brl;
        boff[g] = nrow * 64; bxr[g] = (nrow >> 1) & 3;
    }
    // trans B path (MODE 1)
    const int tmt = lane >> 3, trl = lane & 7;
    const int te_base = ((tmt & 1) << 3) + trl;   // e-row within k16 group
    const int tkc_part = tmt >> 1;                // n8 selector

    float acc[2][4][4];
#pragma unroll
    for (int i = 0; i < 2; i++)
#pragma unroll
        for (int j = 0; j < 4; j++)
#pragma unroll
            for (int q = 0; q < 4; q++) acc[i][j][q] = 0.f;

    LOAD_CHUNK(0, 0); CP_COMMIT();
    LOAD_CHUNK(1, 1); CP_COMMIT();

    for (int c = 0; c < C; c++) {
        CP_WAIT1();
        __syncthreads();
        if (c + 2 < C) { LOAD_CHUNK(c + 2, (c + 2) % NSTAGE); }
        CP_COMMIT();
        const uint32_t sb = sm + (c % NSTAGE) * STAGEB;
#pragma unroll
        for (int ks = 0; ks < 2; ks++) {
            const int kb = ks * 2;
            uint32_t afr[2][4];
            uint32_t afl[2][4];
#pragma unroll
            for (int mi = 0; mi < 2; mi++) {
                ldm4(afr[mi], sb + aoff[mi] + (((kb + ktop) ^ axr[mi]) << 4));
                if (MODE == 0)
                    ldm4(afl[mi], sb + OFFAL + aoff[mi] + (((kb + ktop) ^ axr[mi]) << 4));
            }
#pragma unroll
            for (int g = 0; g < 2; g++) {
                uint32_t bh[4], bl[4];
                if (MODE == 1) {
                    const int e_r = ks * 16 + te_base;
                    const int kc = wn * 4 + g * 2 + tkc_part;
                    uint32_t a0 = sb + OFFBH + e_r * 128 + ((kc ^ trl) << 4);
                    ldm4t(bh, a0);
                    ldm4t(bl, a0 + TILE_BB);
                } else {
                    uint32_t a0 = sb + OFFBH + boff[g] + (((kb + bk2) ^ bxr[g]) << 4);
                    ldm4(bh, a0);
                    ldm4(bl, a0 + TILE_BB);
                }
#pragma unroll
                for (int half = 0; half < 2; half++)     // term Ah*Bh
#pragma unroll
                    for (int mi = 0; mi < 2; mi++)
                        mma16816(acc[mi][g * 2 + half], afr[mi], &bh[half * 2]);
#pragma unroll
                for (int half = 0; half < 2; half++)     // term Ah*Bl
#pragma unroll
                    for (int mi = 0; mi < 2; mi++)
                        mma16816(acc[mi][g * 2 + half], afr[mi], &bl[half * 2]);
                if (MODE == 0) {
#pragma unroll
                    for (int half = 0; half < 2; half++) // term Al*Bh (3-term only)
#pragma unroll
                        for (int mi = 0; mi < 2; mi++)
                            mma16816(acc[mi][g * 2 + half], afl[mi], &bh[half * 2]);
                }
            }
        }
    }
#undef LOAD_CHUNK

    // ---- epilogue from registers
    const int qr = lane >> 2, qc = lane & 3;
#pragma unroll
    for (int mi = 0; mi < 2; mi++)
#pragma unroll
        for (int nj = 0; nj < 4; nj++)
#pragma unroll
            for (int half = 0; half < 2; half++) {
                const int row = m0 + wm * 32 + mi * 16 + qr + half * 8;
                const int col = n0 + wn * 32 + nj * 8 + qc * 2;
                const float v0 = acc[mi][nj][half * 2 + 0];
                const float v1 = acc[mi][nj][half * 2 + 1];
                if (MODE == 0) {
                    float2 o = make_float2(v0 * alpha, v1 * alpha);
                    *(float2*)(Cf + (size_t)b * SEQ * SEQ + (size_t)row * SEQ + col) = o;
                } else if (MODE == 1) {
                    __half2 H;
                    H.x = __float2half_rn(v0);
                    H.y = __float2half_rn(v1);
                    *(__half2*)(g_ch + (size_t)b * SB + (size_t)row * DIM + col) = H;
                } else {
                    const float mk = mask[row];
                    float2 o = make_float2(tanhf(v0 + bias[col]) * mk,
                                           tanhf(v1 + bias[col + 1]) * mk);
                    *(float2*)(Cf + (size_t)row * DIM + col) = o;
                }
            }
}

// ------ fp32 -> fp16 hi/lo split: Q, W, Enc fused in one grid (x4 vec) ------
#define NQ4 (NELEM / 4)
#define NW4 (WELEM / 4)
#define NE4 (NELEM / 4)
__global__ __launch_bounds__(256) void k_split_all(const float4* __restrict__ Qs,
                                                   const float4* __restrict__ Ws,
                                                   const float4* __restrict__ Es)
{
    int i = blockIdx.x * 256 + threadIdx.x;
    const float4* src;
    uint2 *hi, *lo;
    int j;
    if (i < NQ4) { src = Qs; hi = (uint2*)g_qh; lo = (uint2*)g_ql; j = i; }
    else if (i < NQ4 + NW4) { src = Ws; hi = (uint2*)g_wh; lo = (uint2*)g_wl; j = i - NQ4; }
    else if (i < NQ4 + NW4 + NE4) { src = Es; hi = (uint2*)g_eh; lo = (uint2*)g_el; j = i - NQ4 - NW4; }
    else return;
    float4 v = src[j];
    union { __half h[4]; uint2 u; } H, L;
    H.h[0] = __float2half_rn(v.x); L.h[0] = __float2half_rn(v.x - __half2float(H.h[0]));
    H.h[1] = __float2half_rn(v.y); L.h[1] = __float2half_rn(v.y - __half2float(H.h[1]));
    H.h[2] = __float2half_rn(v.z); L.h[2] = __float2half_rn(v.z - __half2float(H.h[2]));
    H.h[3] = __float2half_rn(v.w); L.h[3] = __float2half_rn(v.w - __half2float(H.h[3]));
    hi[j] = H.u; lo[j] = L.u;
}

// ---------- softmax (in place, float4) + fp16 hi out ------------------------
// 2 rows per block, 128 threads/row, 4 elements/thread.
__global__ __launch_bounds__(256) void k_softmax_split(float* __restrict__ w)
{
    const int g = threadIdx.x >> 7;
    const int r = threadIdx.x & 127;
    const size_t rowid = (size_t)blockIdx.x * 2 + g;
    float4* row = (float4*)(w + rowid * SEQ);
    float4 v = row[r];

    __shared__ float red[2][4];
    const int wl = (threadIdx.x >> 5) & 3;

    float m = fmaxf(fmaxf(v.x, v.y), fmaxf(v.z, v.w));
#pragma unroll
    for (int o = 16; o > 0; o >>= 1) m = fmaxf(m, __shfl_xor_sync(0xffffffffu, m, o));
    if ((threadIdx.x & 31) == 0) red[g][wl] = m;
    __syncthreads();
    const float M = fmaxf(fmaxf(red[g][0], red[g][1]), fmaxf(red[g][2], red[g][3]));
    __syncthreads();

    float4 e;
    e.x = __expf(v.x - M); e.y = __expf(v.y - M);
    e.z = __expf(v.z - M); e.w = __expf(v.w - M);
    float s = e.x + e.y + e.z + e.w;
#pragma unroll
    for (int o = 16; o > 0; o >>= 1) s += __shfl_xor_sync(0xffffffffu, s, o);
    if ((threadIdx.x & 31) == 0) red[g][wl] = s;
    __syncthreads();
    const float S = red[g][0] + red[g][1] + red[g][2] + red[g][3];
    const float inv = 1.0f / S;

    e.x *= inv; e.y *= inv; e.z *= inv; e.w *= inv;
    row[r] = e;

    union { __half h[4]; uint2 u; } H;
    H.h[0] = __float2half_rn(e.x);
    H.h[1] = __float2half_rn(e.y);
    H.h[2] = __float2half_rn(e.z);
    H.h[3] = __float2half_rn(e.w);
    ((uint2*)(g_awh + rowid * SEQ))[r] = H.u;
}

// ---------------------------------------------------------------------------
extern "C" void kernel_launch(void* const* d_in, const int* in_sizes, int n_in,
                              void* d_out, int out_size)
{
    const float* Q    = (const float*)d_in[0];
    const float* Enc  = (const float*)d_in[1];
    const float* mask = (const float*)d_in[2];
    const float* W    = (const float*)d_in[3];
    const float* bias = (const float*)d_in[4];

    float* out_masked  = (float*)d_out;
    float* out_weights = (float*)d_out + NELEM;

    static bool attr_done = false;
    if (!attr_done) {
        cudaFuncSetAttribute(k_gemm<0>, cudaFuncAttributeMaxDynamicSharedMemorySize, 3 * 24576);
        cudaFuncSetAttribute(k_gemm<1>, cudaFuncAttributeMaxDynamicSharedMemorySize, 3 * 16384);
        cudaFuncSetAttribute(k_gemm<2>, cudaFuncAttributeMaxDynamicSharedMemorySize, 3 * 16384);
        attr_done = true;
    }

    const float alpha = 1.0f / sqrtf((float)DIM);

    // 1) one fused split kernel (Q, W, Enc -> fp16 hi/lo)
    {
        int total = (int)(NQ4 + NW4 + NE4);
        k_split_all<<<(total + 255) / 256, 256>>>((const float4*)Q, (const float4*)W,
                                                  (const float4*)Enc);
    }
    // 2) scores = alpha * Q @ Enc^T -> out_weights (fp32)  [3-term]
    {
        dim3 g(SEQ / 64, SEQ / 128, BATCH);
        k_gemm<0><<<g, 256, 3 * 24576>>>(out_weights, nullptr, nullptr, alpha);
    }
    // 3) softmax + fp16 hi
    k_softmax_split<<<BATCH * SEQ / 2, 256>>>(out_weights);
    // 4) ctx = AW @ Enc (trans-B) -> g_ch (fp16 hi)  [2-term]
    {
        dim3 g(DIM / 64, SEQ / 128, BATCH);
        k_gemm<1><<<g, 256, 3 * 16384>>>(nullptr, nullptr, nullptr, 1.0f);
    }
    // 5) out = tanh([Q|ctx] @ W^T + bias) * mask  [2-term]
    {
        dim3 g(DIM / 64, (BATCH * SEQ) / 128, 1);
        k_gemm<2><<<g, 256, 3 * 16384>>>(out_masked, bias, mask, 1.0f);
    }
}

// round 11
// speedup vs baseline: 2.6795x; 1.1245x over previous
#include <cuda_runtime.h>
#include <cuda_fp16.h>
#include <cstdint>
#include <math.h>

#define BATCH 32
#define SEQ   512
#define DIM   512

// ---------------- scratch (static device memory; no allocations) ------------
#define NELEM ((size_t)BATCH * SEQ * DIM)          // 8,388,608
#define WELEM ((size_t)DIM * 2 * DIM)              // 524,288
__device__ __align__(16) __half g_qh[NELEM];                // Q hi         [b,q,d]
__device__ __align__(16) __half g_eh[NELEM], g_el[NELEM];   // Enc hi/lo    [b,e,d]
__device__ __align__(16) __half g_awh[NELEM];               // attn weights [b,q,e] (hi)
__device__ __align__(16) __half g_ch[NELEM];                // ctx hi       [b,q,d]
__device__ __align__(16) __half g_wh[WELEM], g_wl[WELEM];   // W hi/lo

// ---------------- PTX helpers (all non-arch-'a'; compile for sm_103) --------
__device__ __forceinline__ uint32_t smem_u32(const void* p) {
    uint32_t a;
    asm("{ .reg .u64 t; cvta.to.shared.u64 t, %1; cvt.u32.u64 %0, t; }" : "=r"(a) : "l"(p));
    return a;
}
__device__ __forceinline__ void cp16(uint32_t dst, const void* src) {
    asm volatile("cp.async.cg.shared.global [%0], [%1], 16;" :: "r"(dst), "l"(src));
}
#define CP_COMMIT() asm volatile("cp.async.commit_group;" ::: "memory")
#define CP_WAIT1()  asm volatile("cp.async.wait_group 1;" ::: "memory")

__device__ __forceinline__ void ldm4(uint32_t* r, uint32_t addr) {
    asm volatile("ldmatrix.sync.aligned.m8n8.x4.shared.b16 {%0,%1,%2,%3}, [%4];"
                 : "=r"(r[0]), "=r"(r[1]), "=r"(r[2]), "=r"(r[3]) : "r"(addr));
}
__device__ __forceinline__ void ldm4t(uint32_t* r, uint32_t addr) {
    asm volatile("ldmatrix.sync.aligned.m8n8.x4.trans.shared.b16 {%0,%1,%2,%3}, [%4];"
                 : "=r"(r[0]), "=r"(r[1]), "=r"(r[2]), "=r"(r[3]) : "r"(addr));
}
__device__ __forceinline__ void mma16816(float* c, const uint32_t* a, const uint32_t* b) {
    asm volatile(
        "mma.sync.aligned.m16n8k16.row.col.f32.f16.f16.f32 "
        "{%0,%1,%2,%3}, {%4,%5,%6,%7}, {%8,%9}, {%0,%1,%2,%3};"
        : "+f"(c[0]), "+f"(c[1]), "+f"(c[2]), "+f"(c[3])
        : "r"(a[0]), "r"(a[1]), "r"(a[2]), "r"(a[3]), "r"(b[0]), "r"(b[1]));
}

// ---------------- GEMM: C = A @ B^T, fp16 2-term (AhBh + AhBl) --------------
// CTA tile 128(m) x 64(n), BK=32. 8 warps = 4m x 2n, warp tile 32x32.
// smem/stage: A 8KB, B hi+lo 8KB = 16KB; 3 stages = 48KB; 3 CTAs/SM.
#define TILE_A   8192           // 128 rows x 64B
#define TILE_BB  4096           // 64 rows x 64B (or 32 rows x 128B for MODE1)
#define OFFBH    TILE_A
#define OFFBL    (TILE_A + TILE_BB)
#define STAGEB   (TILE_A + 2 * TILE_BB)   // 16KB
#define NSTAGE   3
#define SMEM_DYN (NSTAGE * STAGEB)
#define SB ((size_t)SEQ * DIM)

// swizzled byte offset within one NT tile for (row, 16B-chunk kc), 64B rows
__device__ __forceinline__ uint32_t swz(int row, int kc) {
    return (uint32_t)(row * 64 + ((kc ^ ((row >> 1) & 3)) << 4));
}

// MODE 0: scores = alpha * Q @ Enc^T          -> Cf (fp32)
// MODE 1: ctx    = AW @ Enc  (trans-B)        -> g_ch (fp16 hi)
// MODE 2: out    = tanh([Q|ctx] @ W^T + b)*m  -> Cf (fp32)
template <int MODE>
__global__ __launch_bounds__(256, 3) void k_gemm(
    float* __restrict__ Cf, const float* __restrict__ bias,
    const float* __restrict__ mask, float alpha)
{
    extern __shared__ char smem[];
    const uint32_t sm = smem_u32(smem);

    const int tid = threadIdx.x;
    const int lane = tid & 31, wid = tid >> 5;
    const int wm = wid & 3, wn = wid >> 2;       // 4 m-warps x 2 n-warps
    const int b  = blockIdx.z;
    const int m0 = blockIdx.y * 128;
    const int n0 = blockIdx.x * 64;

    const __half *Ah, *A2h = nullptr, *Bh, *Bl;
    int K, lda, ldb;
    if (MODE == 0) {
        Ah = g_qh + (size_t)b * SB;
        Bh = g_eh + (size_t)b * SB;  Bl = g_el + (size_t)b * SB;
        K = DIM; lda = DIM; ldb = DIM;
    } else if (MODE == 1) {
        Ah = g_awh + (size_t)b * SB;
        Bh = g_eh + (size_t)b * SB;  Bl = g_el + (size_t)b * SB;   // [e][d] plain
        K = SEQ; lda = SEQ; ldb = DIM;
    } else {
        Ah = g_qh;  A2h = g_ch;      // rows indexed by global m (0..16383)
        Bh = g_wh;  Bl = g_wl;
        K = 2 * DIM; lda = DIM; ldb = 2 * DIM;
    }
    const int C = K >> 5;   // chunks of 32

#define LOAD_CHUNK(c, stg)                                                       \
    do {                                                                         \
        const int k0_ = (c) * 32;                                                \
        const __half* ah_; int ka_;                                              \
        if (MODE == 2 && k0_ >= DIM) { ah_ = A2h; ka_ = k0_ - DIM; }             \
        else                         { ah_ = Ah;  ka_ = k0_; }                   \
        const uint32_t sb_ = sm + (stg) * STAGEB;                                \
        _Pragma("unroll")                                                        \
        for (int i_ = 0; i_ < 2; i_++) {  /* A hi: 128 rows x 4 kc = 512 */      \
            int idx_ = i_ * 256 + tid;                                           \
            int row_ = idx_ >> 2, kc_ = idx_ & 3;                                \
            uint32_t d_ = swz(row_, kc_);                                        \
            cp16(sb_ + d_, (const char*)(ah_ + (size_t)(m0 + row_) * lda + ka_) + kc_ * 16); \
        }                                                                        \
        if (MODE == 1) {                                                         \
            /* B tile: 32 e-rows x 128B ([e][d] slice), 256 chunks */            \
            int row_ = tid >> 3, kc_ = tid & 7;                                  \
            uint32_t d_ = (uint32_t)(row_ * 128 + ((kc_ ^ (row_ & 7)) << 4));    \
            cp16(sb_ + OFFBH + d_, (const char*)(Bh + (size_t)(k0_ + row_) * ldb + n0) + kc_ * 16); \
            cp16(sb_ + OFFBL + d_, (const char*)(Bl + (size_t)(k0_ + row_) * ldb + n0) + kc_ * 16); \
        } else {                                                                 \
            /* B tile: 64 n-rows x 4 kc = 256 chunks */                          \
            int row_ = tid >> 2, kc_ = tid & 3;                                  \
            uint32_t d_ = swz(row_, kc_);                                        \
            cp16(sb_ + OFFBH + d_, (const char*)(Bh + (size_t)(n0 + row_) * ldb + k0_) + kc_ * 16); \
            cp16(sb_ + OFFBL + d_, (const char*)(Bl + (size_t)(n0 + row_) * ldb + k0_) + kc_ * 16); \
        }                                                                        \
    } while (0)

    // ---- per-lane ldmatrix address precomputes
    const int ar = lane & 15, ktop = lane >> 4;
    int aoff[2], axr[2];
#pragma unroll
    for (int mi = 0; mi < 2; mi++) {
        int row = wm * 32 + mi * 16 + ar;
        aoff[mi] = row * 64; axr[mi] = (row >> 1) & 3;
    }
    // NT B path (MODE 0/2): 2 groups of 16 n-rows per warp
    const int brl = ((lane >> 4) << 3) + (lane & 7);
    const int bk2 = (lane >> 3) & 1;
    int boff[2], bxr[2];
#pragma unroll
    for (int g = 0; g < 2; g++) {
        int nrow = wn * 32 + g * 16 + brl;
        boff[g] = nrow * 64; bxr[g] = (nrow >> 1) & 3;
    }
    // trans B path (MODE 1)
    const int tmt = lane >> 3, trl = lane & 7;
    const int te_base = ((tmt & 1) << 3) + trl;   // e-row within k16 group
    const int tkc_part = tmt >> 1;                // n8 selector

    float acc[2][4][4];
#pragma unroll
    for (int i = 0; i < 2; i++)
#pragma unroll
        for (int j = 0; j < 4; j++)
#pragma unroll
            for (int q = 0; q < 4; q++) acc[i][j][q] = 0.f;

    LOAD_CHUNK(0, 0); CP_COMMIT();
    LOAD_CHUNK(1, 1); CP_COMMIT();

    for (int c = 0; c < C; c++) {
        CP_WAIT1();
        __syncthreads();
        if (c + 2 < C) { LOAD_CHUNK(c + 2, (c + 2) % NSTAGE); }
        CP_COMMIT();
        const uint32_t sb = sm + (c % NSTAGE) * STAGEB;
#pragma unroll
        for (int ks = 0; ks < 2; ks++) {
            const int kb = ks * 2;
            uint32_t afr[2][4];
#pragma unroll
            for (int mi = 0; mi < 2; mi++)
                ldm4(afr[mi], sb + aoff[mi] + (((kb + ktop) ^ axr[mi]) << 4));
#pragma unroll
            for (int g = 0; g < 2; g++) {
                uint32_t bh[4], bl[4];
                if (MODE == 1) {
                    const int e_r = ks * 16 + te_base;
                    const int kc = wn * 4 + g * 2 + tkc_part;
                    uint32_t a0 = sb + OFFBH + e_r * 128 + ((kc ^ trl) << 4);
                    ldm4t(bh, a0);
                    ldm4t(bl, a0 + TILE_BB);
                } else {
                    uint32_t a0 = sb + OFFBH + boff[g] + (((kb + bk2) ^ bxr[g]) << 4);
                    ldm4(bh, a0);
                    ldm4(bl, a0 + TILE_BB);
                }
#pragma unroll
                for (int half = 0; half < 2; half++)     // term Ah*Bh
#pragma unroll
                    for (int mi = 0; mi < 2; mi++)
                        mma16816(acc[mi][g * 2 + half], afr[mi], &bh[half * 2]);
#pragma unroll
                for (int half = 0; half < 2; half++)     // term Ah*Bl
#pragma unroll
                    for (int mi = 0; mi < 2; mi++)
                        mma16816(acc[mi][g * 2 + half], afr[mi], &bl[half * 2]);
            }
        }
    }
#undef LOAD_CHUNK

    // ---- epilogue from registers
    const int qr = lane >> 2, qc = lane & 3;
#pragma unroll
    for (int mi = 0; mi < 2; mi++)
#pragma unroll
        for (int nj = 0; nj < 4; nj++)
#pragma unroll
            for (int half = 0; half < 2; half++) {
                const int row = m0 + wm * 32 + mi * 16 + qr + half * 8;
                const int col = n0 + wn * 32 + nj * 8 + qc * 2;
                const float v0 = acc[mi][nj][half * 2 + 0];
                const float v1 = acc[mi][nj][half * 2 + 1];
                if (MODE == 0) {
                    float2 o = make_float2(v0 * alpha, v1 * alpha);
                    *(float2*)(Cf + (size_t)b * SEQ * SEQ + (size_t)row * SEQ + col) = o;
                } else if (MODE == 1) {
                    __half2 H;
                    H.x = __float2half_rn(v0);
                    H.y = __float2half_rn(v1);
                    *(__half2*)(g_ch + (size_t)b * SB + (size_t)row * DIM + col) = H;
                } else {
                    const float mk = mask[row];
                    float2 o = make_float2(tanhf(v0 + bias[col]) * mk,
                                           tanhf(v1 + bias[col + 1]) * mk);
                    *(float2*)(Cf + (size_t)row * DIM + col) = o;
                }
            }
}

// ------ fp32 -> fp16 split: Q (hi only), W (hi/lo), Enc (hi/lo) -------------
#define NQ4 (NELEM / 4)
#define NW4 (WELEM / 4)
#define NE4 (NELEM / 4)
__global__ __launch_bounds__(256) void k_split_all(const float4* __restrict__ Qs,
                                                   const float4* __restrict__ Ws,
                                                   const float4* __restrict__ Es)
{
    int i = blockIdx.x * 256 + threadIdx.x;
    const float4* src;
    uint2 *hi, *lo;
    int j;
    if (i < NQ4) { src = Qs; hi = (uint2*)g_qh; lo = nullptr; j = i; }
    else if (i < NQ4 + NW4) { src = Ws; hi = (uint2*)g_wh; lo = (uint2*)g_wl; j = i - NQ4; }
    else if (i < NQ4 + NW4 + NE4) { src = Es; hi = (uint2*)g_eh; lo = (uint2*)g_el; j = i - NQ4 - NW4; }
    else return;
    float4 v = src[j];
    union { __half h[4]; uint2 u; } H, L;
    H.h[0] = __float2half_rn(v.x);
    H.h[1] = __float2half_rn(v.y);
    H.h[2] = __float2half_rn(v.z);
    H.h[3] = __float2half_rn(v.w);
    hi[j] = H.u;
    if (lo) {
        L.h[0] = __float2half_rn(v.x - __half2float(H.h[0]));
        L.h[1] = __float2half_rn(v.y - __half2float(H.h[1]));
        L.h[2] = __float2half_rn(v.z - __half2float(H.h[2]));
        L.h[3] = __float2half_rn(v.w - __half2float(H.h[3]));
        lo[j] = L.u;
    }
}

// ---------- softmax (in place, float4) + fp16 hi out ------------------------
// 2 rows per block, 128 threads/row, 4 elements/thread.
__global__ __launch_bounds__(256) void k_softmax_split(float* __restrict__ w)
{
    const int g = threadIdx.x >> 7;
    const int r = threadIdx.x & 127;
    const size_t rowid = (size_t)blockIdx.x * 2 + g;
    float4* row = (float4*)(w + rowid * SEQ);
    float4 v = row[r];

    __shared__ float red[2][4];
    const int wl = (threadIdx.x >> 5) & 3;

    float m = fmaxf(fmaxf(v.x, v.y), fmaxf(v.z, v.w));
#pragma unroll
    for (int o = 16; o > 0; o >>= 1) m = fmaxf(m, __shfl_xor_sync(0xffffffffu, m, o));
    if ((threadIdx.x & 31) == 0) red[g][wl] = m;
    __syncthreads();
    const float M = fmaxf(fmaxf(red[g][0], red[g][1]), fmaxf(red[g][2], red[g][3]));
    __syncthreads();

    float4 e;
    e.x = __expf(v.x - M); e.y = __expf(v.y - M);
    e.z = __expf(v.z - M); e.w = __expf(v.w - M);
    float s = e.x + e.y + e.z + e.w;
#pragma unroll
    for (int o = 16; o > 0; o >>= 1) s += __shfl_xor_sync(0xffffffffu, s, o);
    if ((threadIdx.x & 31) == 0) red[g][wl] = s;
    __syncthreads();
    const float S = red[g][0] + red[g][1] + red[g][2] + red[g][3];
    const float inv = 1.0f / S;

    e.x *= inv; e.y *= inv; e.z *= inv; e.w *= inv;
    row[r] = e;

    union { __half h[4]; uint2 u; } H;
    H.h[0] = __float2half_rn(e.x);
    H.h[1] = __float2half_rn(e.y);
    H.h[2] = __float2half_rn(e.z);
    H.h[3] = __float2half_rn(e.w);
    ((uint2*)(g_awh + rowid * SEQ))[r] = H.u;
}

// ---------------------------------------------------------------------------
extern "C" void kernel_launch(void* const* d_in, const int* in_sizes, int n_in,
                              void* d_out, int out_size)
{
    const float* Q    = (const float*)d_in[0];
    const float* Enc  = (const float*)d_in[1];
    const float* mask = (const float*)d_in[2];
    const float* W    = (const float*)d_in[3];
    const float* bias = (const float*)d_in[4];

    float* out_masked  = (float*)d_out;
    float* out_weights = (float*)d_out + NELEM;

    static bool attr_done = false;
    if (!attr_done) {
        cudaFuncSetAttribute(k_gemm<0>, cudaFuncAttributeMaxDynamicSharedMemorySize, SMEM_DYN);
        cudaFuncSetAttribute(k_gemm<1>, cudaFuncAttributeMaxDynamicSharedMemorySize, SMEM_DYN);
        cudaFuncSetAttribute(k_gemm<2>, cudaFuncAttributeMaxDynamicSharedMemorySize, SMEM_DYN);
        attr_done = true;
    }

    const float alpha = 1.0f / sqrtf((float)DIM);

    // 1) one fused split kernel (Q hi; W, Enc hi/lo)
    {
        int total = (int)(NQ4 + NW4 + NE4);
        k_split_all<<<(total + 255) / 256, 256>>>((const float4*)Q, (const float4*)W,
                                                  (const float4*)Enc);
    }
    // 2) scores = alpha * Q @ Enc^T -> out_weights (fp32)
    {
        dim3 g(SEQ / 64, SEQ / 128, BATCH);
        k_gemm<0><<<g, 256, SMEM_DYN>>>(out_weights, nullptr, nullptr, alpha);
    }
    // 3) softmax + fp16 hi
    k_softmax_split<<<BATCH * SEQ / 2, 256>>>(out_weights);
    // 4) ctx = AW @ Enc (trans-B) -> g_ch (fp16 hi)
    {
        dim3 g(DIM / 64, SEQ / 128, BATCH);
        k_gemm<1><<<g, 256, SMEM_DYN>>>(nullptr, nullptr, nullptr, 1.0f);
    }
    // 5) out = tanh([Q|ctx] @ W^T + bias) * mask
    {
        dim3 g(DIM / 64, (BATCH * SEQ) / 128, 1);
        k_gemm<2><<<g, 256, SMEM_DYN>>>(out_masked, bias, mask, 1.0f);
    }
}

// round 12
// speedup vs baseline: 3.6393x; 1.3582x over previous
#include <cuda_runtime.h>
#include <cuda_fp16.h>
#include <cstdint>
#include <math.h>

#define BATCH 32
#define SEQ   512
#define DIM   512

// ---------------- scratch (static device memory; no allocations) ------------
#define NELEM ((size_t)BATCH * SEQ * DIM)          // 8,388,608
#define WELEM ((size_t)DIM * 2 * DIM)              // 524,288
__device__ __align__(16) __half g_qh[NELEM];                // Q hi         [b,q,d]
__device__ __align__(16) __half g_eh[NELEM], g_el[NELEM];   // Enc hi/lo    [b,e,d]
__device__ __align__(16) __half g_awh[NELEM];               // attn weights [b,q,e] (hi)
__device__ __align__(16) __half g_ch[NELEM];                // ctx hi       [b,q,d]
__device__ __align__(16) __half g_wh[WELEM];                // W hi

// ---------------- PTX helpers (all non-arch-'a'; compile for sm_103) --------
__device__ __forceinline__ uint32_t smem_u32(const void* p) {
    uint32_t a;
    asm("{ .reg .u64 t; cvta.to.shared.u64 t, %1; cvt.u32.u64 %0, t; }" : "=r"(a) : "l"(p));
    return a;
}
__device__ __forceinline__ void cp16(uint32_t dst, const void* src) {
    asm volatile("cp.async.cg.shared.global [%0], [%1], 16;" :: "r"(dst), "l"(src));
}
#define CP_COMMIT() asm volatile("cp.async.commit_group;" ::: "memory")
#define CP_WAIT1()  asm volatile("cp.async.wait_group 1;" ::: "memory")

__device__ __forceinline__ void ldm4(uint32_t* r, uint32_t addr) {
    asm volatile("ldmatrix.sync.aligned.m8n8.x4.shared.b16 {%0,%1,%2,%3}, [%4];"
                 : "=r"(r[0]), "=r"(r[1]), "=r"(r[2]), "=r"(r[3]) : "r"(addr));
}
__device__ __forceinline__ void ldm4t(uint32_t* r, uint32_t addr) {
    asm volatile("ldmatrix.sync.aligned.m8n8.x4.trans.shared.b16 {%0,%1,%2,%3}, [%4];"
                 : "=r"(r[0]), "=r"(r[1]), "=r"(r[2]), "=r"(r[3]) : "r"(addr));
}
__device__ __forceinline__ void mma16816(float* c, const uint32_t* a, const uint32_t* b) {
    asm volatile(
        "mma.sync.aligned.m16n8k16.row.col.f32.f16.f16.f32 "
        "{%0,%1,%2,%3}, {%4,%5,%6,%7}, {%8,%9}, {%0,%1,%2,%3};"
        : "+f"(c[0]), "+f"(c[1]), "+f"(c[2]), "+f"(c[3])
        : "r"(a[0]), "r"(a[1]), "r"(a[2]), "r"(a[3]), "r"(b[0]), "r"(b[1]));
}

// ---------------- GEMM: C = A @ B^T, fp16 -----------------------------------
// CTA tile 128(m) x 64(n), BK=32. 8 warps = 4m x 2n, warp tile 32x32.
// MODE 0: 2-term (AhBh + AhBl). stage 16KB. MODE 1/2: 1-term. stage 12KB.
#define TILE_A   8192           // 128 rows x 64B
#define TILE_BB  4096           // 64 rows x 64B (or 32 rows x 128B for MODE1)
#define NSTAGE   3
#define SB ((size_t)SEQ * DIM)

// swizzled byte offset within one NT tile for (row, 16B-chunk kc), 64B rows
__device__ __forceinline__ uint32_t swz(int row, int kc) {
    return (uint32_t)(row * 64 + ((kc ^ ((row >> 1) & 3)) << 4));
}

// MODE 0: scores = alpha * Q @ Enc^T          -> Cf (fp32)      [2-term]
// MODE 1: ctx    = AW @ Enc  (trans-B)        -> g_ch (fp16 hi) [1-term]
// MODE 2: out    = tanh([Q|ctx] @ W^T + b)*m  -> Cf (fp32)      [1-term]
template <int MODE>
__global__ __launch_bounds__(256, 3) void k_gemm(
    float* __restrict__ Cf, const float* __restrict__ bias,
    const float* __restrict__ mask, float alpha)
{
    constexpr bool TWO = (MODE == 0);
    constexpr int OFFBH  = TILE_A;
    constexpr int OFFBL  = TILE_A + TILE_BB;
    constexpr int STAGEB = TILE_A + (TWO ? 2 : 1) * TILE_BB;

    extern __shared__ char smem[];
    const uint32_t sm = smem_u32(smem);

    const int tid = threadIdx.x;
    const int lane = tid & 31, wid = tid >> 5;
    const int wm = wid & 3, wn = wid >> 2;       // 4 m-warps x 2 n-warps
    const int b  = blockIdx.z;
    const int m0 = blockIdx.y * 128;
    const int n0 = blockIdx.x * 64;

    const __half *Ah, *A2h = nullptr, *Bh, *Bl = nullptr;
    int K, lda, ldb;
    if (MODE == 0) {
        Ah = g_qh + (size_t)b * SB;
        Bh = g_eh + (size_t)b * SB;  Bl = g_el + (size_t)b * SB;
        K = DIM; lda = DIM; ldb = DIM;
    } else if (MODE == 1) {
        Ah = g_awh + (size_t)b * SB;
        Bh = g_eh + (size_t)b * SB;                                // [e][d] plain
        K = SEQ; lda = SEQ; ldb = DIM;
    } else {
        Ah = g_qh;  A2h = g_ch;      // rows indexed by global m (0..16383)
        Bh = g_wh;
        K = 2 * DIM; lda = DIM; ldb = 2 * DIM;
    }
    const int C = K >> 5;   // chunks of 32

#define LOAD_CHUNK(c, stg)                                                       \
    do {                                                                         \
        const int k0_ = (c) * 32;                                                \
        const __half* ah_; int ka_;                                              \
        if (MODE == 2 && k0_ >= DIM) { ah_ = A2h; ka_ = k0_ - DIM; }             \
        else                         { ah_ = Ah;  ka_ = k0_; }                   \
        const uint32_t sb_ = sm + (stg) * STAGEB;                                \
        _Pragma("unroll")                                                        \
        for (int i_ = 0; i_ < 2; i_++) {  /* A hi: 128 rows x 4 kc = 512 */      \
            int idx_ = i_ * 256 + tid;                                           \
            int row_ = idx_ >> 2, kc_ = idx_ & 3;                                \
            uint32_t d_ = swz(row_, kc_);                                        \
            cp16(sb_ + d_, (const char*)(ah_ + (size_t)(m0 + row_) * lda + ka_) + kc_ * 16); \
        }                                                                        \
        if (MODE == 1) {                                                         \
            /* B tile: 32 e-rows x 128B ([e][d] slice), 256 chunks */            \
            int row_ = tid >> 3, kc_ = tid & 7;                                  \
            uint32_t d_ = (uint32_t)(row_ * 128 + ((kc_ ^ (row_ & 7)) << 4));    \
            cp16(sb_ + OFFBH + d_, (const char*)(Bh + (size_t)(k0_ + row_) * ldb + n0) + kc_ * 16); \
        } else {                                                                 \
            /* B tile: 64 n-rows x 4 kc = 256 chunks */                          \
            int row_ = tid >> 2, kc_ = tid & 3;                                  \
            uint32_t d_ = swz(row_, kc_);                                        \
            cp16(sb_ + OFFBH + d_, (const char*)(Bh + (size_t)(n0 + row_) * ldb + k0_) + kc_ * 16); \
            if (TWO)                                                             \
                cp16(sb_ + OFFBL + d_, (const char*)(Bl + (size_t)(n0 + row_) * ldb + k0_) + kc_ * 16); \
        }                                                                        \
    } while (0)

    // ---- per-lane ldmatrix address precomputes
    const int ar = lane & 15, ktop = lane >> 4;
    int aoff[2], axr[2];
#pragma unroll
    for (int mi = 0; mi < 2; mi++) {
        int row = wm * 32 + mi * 16 + ar;
        aoff[mi] = row * 64; axr[mi] = (row >> 1) & 3;
    }
    // NT B path (MODE 0/2): 2 groups of 16 n-rows per warp
    const int brl = ((lane >> 4) << 3) + (lane & 7);
    const int bk2 = (lane >> 3) & 1;
    int boff[2], bxr[2];
#pragma unroll
    for (int g = 0; g < 2; g++) {
        int nrow = wn * 32 + g * 16 + brl;
        boff[g] = nrow * 64; bxr[g] = (nrow >> 1) & 3;
    }
    // trans B path (MODE 1)
    const int tmt = lane >> 3, trl = lane & 7;
    const int te_base = ((tmt & 1) << 3) + trl;   // e-row within k16 group
    const int tkc_part = tmt >> 1;                // n8 selector

    float acc[2][4][4];
#pragma unroll
    for (int i = 0; i < 2; i++)
#pragma unroll
        for (int j = 0; j < 4; j++)
#pragma unroll
            for (int q = 0; q < 4; q++) acc[i][j][q] = 0.f;

    LOAD_CHUNK(0, 0); CP_COMMIT();
    LOAD_CHUNK(1, 1); CP_COMMIT();

    for (int c = 0; c < C; c++) {
        CP_WAIT1();
        __syncthreads();
        if (c + 2 < C) { LOAD_CHUNK(c + 2, (c + 2) % NSTAGE); }
        CP_COMMIT();
        const uint32_t sb = sm + (c % NSTAGE) * STAGEB;
#pragma unroll
        for (int ks = 0; ks < 2; ks++) {
            const int kb = ks * 2;
            uint32_t afr[2][4];
#pragma unroll
            for (int mi = 0; mi < 2; mi++)
                ldm4(afr[mi], sb + aoff[mi] + (((kb + ktop) ^ axr[mi]) << 4));
#pragma unroll
            for (int g = 0; g < 2; g++) {
                uint32_t bh[4], bl[4];
                if (MODE == 1) {
                    const int e_r = ks * 16 + te_base;
                    const int kc = wn * 4 + g * 2 + tkc_part;
                    ldm4t(bh, sb + OFFBH + e_r * 128 + ((kc ^ trl) << 4));
                } else {
                    uint32_t a0 = sb + OFFBH + boff[g] + (((kb + bk2) ^ bxr[g]) << 4);
                    ldm4(bh, a0);
                    if (TWO) ldm4(bl, a0 + TILE_BB);
                }
#pragma unroll
                for (int half = 0; half < 2; half++)     // term Ah*Bh
#pragma unroll
                    for (int mi = 0; mi < 2; mi++)
                        mma16816(acc[mi][g * 2 + half], afr[mi], &bh[half * 2]);
                if (TWO) {
#pragma unroll
                    for (int half = 0; half < 2; half++) // term Ah*Bl
#pragma unroll
                        for (int mi = 0; mi < 2; mi++)
                            mma16816(acc[mi][g * 2 + half], afr[mi], &bl[half * 2]);
                }
            }
        }
    }
#undef LOAD_CHUNK

    // ---- epilogue from registers
    const int qr = lane >> 2, qc = lane & 3;
#pragma unroll
    for (int mi = 0; mi < 2; mi++)
#pragma unroll
        for (int nj = 0; nj < 4; nj++)
#pragma unroll
            for (int half = 0; half < 2; half++) {
                const int row = m0 + wm * 32 + mi * 16 + qr + half * 8;
                const int col = n0 + wn * 32 + nj * 8 + qc * 2;
                const float v0 = acc[mi][nj][half * 2 + 0];
                const float v1 = acc[mi][nj][half * 2 + 1];
                if (MODE == 0) {
                    float2 o = make_float2(v0 * alpha, v1 * alpha);
                    *(float2*)(Cf + (size_t)b * SEQ * SEQ + (size_t)row * SEQ + col) = o;
                } else if (MODE == 1) {
                    __half2 H;
                    H.x = __float2half_rn(v0);
                    H.y = __float2half_rn(v1);
                    *(__half2*)(g_ch + (size_t)b * SB + (size_t)row * DIM + col) = H;
                } else {
                    const float mk = mask[row];
                    float2 o = make_float2(tanhf(v0 + bias[col]) * mk,
                                           tanhf(v1 + bias[col + 1]) * mk);
                    *(float2*)(Cf + (size_t)row * DIM + col) = o;
                }
            }
}

// ------ fp32 -> fp16 split: Q hi, W hi, Enc hi/lo ---------------------------
#define NQ4 (NELEM / 4)
#define NW4 (WELEM / 4)
#define NE4 (NELEM / 4)
__global__ __launch_bounds__(256) void k_split_all(const float4* __restrict__ Qs,
                                                   const float4* __restrict__ Ws,
                                                   const float4* __restrict__ Es)
{
    int i = blockIdx.x * 256 + threadIdx.x;
    const float4* src;
    uint2 *hi, *lo;
    int j;
    if (i < NQ4) { src = Qs; hi = (uint2*)g_qh; lo = nullptr; j = i; }
    else if (i < NQ4 + NW4) { src = Ws; hi = (uint2*)g_wh; lo = nullptr; j = i - NQ4; }
    else if (i < NQ4 + NW4 + NE4) { src = Es; hi = (uint2*)g_eh; lo = (uint2*)g_el; j = i - NQ4 - NW4; }
    else return;
    float4 v = src[j];
    union { __half h[4]; uint2 u; } H, L;
    H.h[0] = __float2half_rn(v.x);
    H.h[1] = __float2half_rn(v.y);
    H.h[2] = __float2half_rn(v.z);
    H.h[3] = __float2half_rn(v.w);
    hi[j] = H.u;
    if (lo) {
        L.h[0] = __float2half_rn(v.x - __half2float(H.h[0]));
        L.h[1] = __float2half_rn(v.y - __half2float(H.h[1]));
        L.h[2] = __float2half_rn(v.z - __half2float(H.h[2]));
        L.h[3] = __float2half_rn(v.w - __half2float(H.h[3]));
        lo[j] = L.u;
    }
}

// ---------- softmax (in place, float4) + fp16 hi out ------------------------
// 2 rows per block, 128 threads/row, 4 elements/thread.
__global__ __launch_bounds__(256) void k_softmax_split(float* __restrict__ w)
{
    const int g = threadIdx.x >> 7;
    const int r = threadIdx.x & 127;
    const size_t rowid = (size_t)blockIdx.x * 2 + g;
    float4* row = (float4*)(w + rowid * SEQ);
    float4 v = row[r];

    __shared__ float red[2][4];
    const int wl = (threadIdx.x >> 5) & 3;

    float m = fmaxf(fmaxf(v.x, v.y), fmaxf(v.z, v.w));
#pragma unroll
    for (int o = 16; o > 0; o >>= 1) m = fmaxf(m, __shfl_xor_sync(0xffffffffu, m, o));
    if ((threadIdx.x & 31) == 0) red[g][wl] = m;
    __syncthreads();
    const float M = fmaxf(fmaxf(red[g][0], red[g][1]), fmaxf(red[g][2], red[g][3]));
    __syncthreads();

    float4 e;
    e.x = __expf(v.x - M); e.y = __expf(v.y - M);
    e.z = __expf(v.z - M); e.w = __expf(v.w - M);
    float s = e.x + e.y + e.z + e.w;
#pragma unroll
    for (int o = 16; o > 0; o >>= 1) s += __shfl_xor_sync(0xffffffffu, s, o);
    if ((threadIdx.x & 31) == 0) red[g][wl] = s;
    __syncthreads();
    const float S = red[g][0] + red[g][1] + red[g][2] + red[g][3];
    const float inv = 1.0f / S;

    e.x *= inv; e.y *= inv; e.z *= inv; e.w *= inv;
    row[r] = e;

    union { __half h[4]; uint2 u; } H;
    H.h[0] = __float2half_rn(e.x);
    H.h[1] = __float2half_rn(e.y);
    H.h[2] = __float2half_rn(e.z);
    H.h[3] = __float2half_rn(e.w);
    ((uint2*)(g_awh + rowid * SEQ))[r] = H.u;
}

// ---------------------------------------------------------------------------
extern "C" void kernel_launch(void* const* d_in, const int* in_sizes, int n_in,
                              void* d_out, int out_size)
{
    const float* Q    = (const float*)d_in[0];
    const float* Enc  = (const float*)d_in[1];
    const float* mask = (const float*)d_in[2];
    const float* W    = (const float*)d_in[3];
    const float* bias = (const float*)d_in[4];

    float* out_masked  = (float*)d_out;
    float* out_weights = (float*)d_out + NELEM;

    static bool attr_done = false;
    if (!attr_done) {
        cudaFuncSetAttribute(k_gemm<0>, cudaFuncAttributeMaxDynamicSharedMemorySize, 3 * 16384);
        cudaFuncSetAttribute(k_gemm<1>, cudaFuncAttributeMaxDynamicSharedMemorySize, 3 * 12288);
        cudaFuncSetAttribute(k_gemm<2>, cudaFuncAttributeMaxDynamicSharedMemorySize, 3 * 12288);
        attr_done = true;
    }

    const float alpha = 1.0f / sqrtf((float)DIM);

    // 1) one fused split kernel (Q hi; W hi; Enc hi/lo)
    {
        int total = (int)(NQ4 + NW4 + NE4);
        k_split_all<<<(total + 255) / 256, 256>>>((const float4*)Q, (const float4*)W,
                                                  (const float4*)Enc);
    }
    // 2) scores = alpha * Q @ Enc^T -> out_weights (fp32)  [2-term]
    {
        dim3 g(SEQ / 64, SEQ / 128, BATCH);
        k_gemm<0><<<g, 256, 3 * 16384>>>(out_weights, nullptr, nullptr, alpha);
    }
    // 3) softmax + fp16 hi
    k_softmax_split<<<BATCH * SEQ / 2, 256>>>(out_weights);
    // 4) ctx = AW @ Enc (trans-B) -> g_ch (fp16 hi)  [1-term]
    {
        dim3 g(DIM / 64, SEQ / 128, BATCH);
        k_gemm<1><<<g, 256, 3 * 12288>>>(nullptr, nullptr, nullptr, 1.0f);
    }
    // 5) out = tanh([Q|ctx] @ W^T + bias) * mask  [1-term]
    {
        dim3 g(DIM / 64, (BATCH * SEQ) / 128, 1);
        k_gemm<2><<<g, 256, 3 * 12288>>>(out_masked, bias, mask, 1.0f);
    }
}

// round 13
// speedup vs baseline: 4.0268x; 1.1065x over previous
#include <cuda_runtime.h>
#include <cuda_fp16.h>
#include <cstdint>
#include <math.h>

#define BATCH 32
#define SEQ   512
#define DIM   512

// ---------------- scratch (static device memory; no allocations) ------------
#define NELEM ((size_t)BATCH * SEQ * DIM)          // 8,388,608
#define WELEM ((size_t)DIM * 2 * DIM)              // 524,288
__device__ __align__(16) __half g_qh[NELEM];                // Q fp16       [b,q,d]
__device__ __align__(16) __half g_eh[NELEM];                // Enc fp16     [b,e,d]
__device__ __align__(16) __half g_awh[NELEM];               // attn weights [b,q,e]
__device__ __align__(16) __half g_ch[NELEM];                // ctx fp16     [b,q,d]
__device__ __align__(16) __half g_wh[WELEM];                // W fp16

// ---------------- PTX helpers (all non-arch-'a'; compile for sm_103) --------
__device__ __forceinline__ uint32_t smem_u32(const void* p) {
    uint32_t a;
    asm("{ .reg .u64 t; cvta.to.shared.u64 t, %1; cvt.u32.u64 %0, t; }" : "=r"(a) : "l"(p));
    return a;
}
__device__ __forceinline__ void cp16(uint32_t dst, const void* src) {
    asm volatile("cp.async.cg.shared.global [%0], [%1], 16;" :: "r"(dst), "l"(src));
}
#define CP_COMMIT() asm volatile("cp.async.commit_group;" ::: "memory")
#define CP_WAIT1()  asm volatile("cp.async.wait_group 1;" ::: "memory")

__device__ __forceinline__ void ldm4(uint32_t* r, uint32_t addr) {
    asm volatile("ldmatrix.sync.aligned.m8n8.x4.shared.b16 {%0,%1,%2,%3}, [%4];"
                 : "=r"(r[0]), "=r"(r[1]), "=r"(r[2]), "=r"(r[3]) : "r"(addr));
}
__device__ __forceinline__ void ldm4t(uint32_t* r, uint32_t addr) {
    asm volatile("ldmatrix.sync.aligned.m8n8.x4.trans.shared.b16 {%0,%1,%2,%3}, [%4];"
                 : "=r"(r[0]), "=r"(r[1]), "=r"(r[2]), "=r"(r[3]) : "r"(addr));
}
__device__ __forceinline__ void mma16816(float* c, const uint32_t* a, const uint32_t* b) {
    asm volatile(
        "mma.sync.aligned.m16n8k16.row.col.f32.f16.f16.f32 "
        "{%0,%1,%2,%3}, {%4,%5,%6,%7}, {%8,%9}, {%0,%1,%2,%3};"
        : "+f"(c[0]), "+f"(c[1]), "+f"(c[2]), "+f"(c[3])
        : "r"(a[0]), "r"(a[1]), "r"(a[2]), "r"(a[3]), "r"(b[0]), "r"(b[1]));
}

// ---------------- GEMM: C = A @ B^T, fp16 1-term -----------------------------
// CTA tile 128(m) x 64(n), BK=32. 8 warps = 4m x 2n, warp tile 32x32.
// smem/stage: A 8KB + B 4KB = 12KB; 3 stages = 36KB; 3 CTAs/SM.
#define TILE_A   8192           // 128 rows x 64B
#define TILE_BB  4096           // 64 rows x 64B (or 32 rows x 128B for MODE1)
#define OFFBH    TILE_A
#define STAGEB   (TILE_A + TILE_BB)   // 12KB
#define NSTAGE   3
#define SMEM_DYN (NSTAGE * STAGEB)
#define SB ((size_t)SEQ * DIM)

// swizzled byte offset within one NT tile for (row, 16B-chunk kc), 64B rows
__device__ __forceinline__ uint32_t swz(int row, int kc) {
    return (uint32_t)(row * 64 + ((kc ^ ((row >> 1) & 3)) << 4));
}

// MODE 0: scores = alpha * Q @ Enc^T          -> Cf (fp32)
// MODE 1: ctx    = AW @ Enc  (trans-B)        -> g_ch (fp16)
// MODE 2: out    = tanh([Q|ctx] @ W^T + b)*m  -> Cf (fp32)
template <int MODE>
__global__ __launch_bounds__(256, 3) void k_gemm(
    float* __restrict__ Cf, const float* __restrict__ bias,
    const float* __restrict__ mask, float alpha)
{
    extern __shared__ char smem[];
    const uint32_t sm = smem_u32(smem);

    const int tid = threadIdx.x;
    const int lane = tid & 31, wid = tid >> 5;
    const int wm = wid & 3, wn = wid >> 2;       // 4 m-warps x 2 n-warps
    const int b  = blockIdx.z;
    const int m0 = blockIdx.y * 128;
    const int n0 = blockIdx.x * 64;

    const __half *Ah, *A2h = nullptr, *Bh;
    int K, lda, ldb;
    if (MODE == 0) {
        Ah = g_qh + (size_t)b * SB;
        Bh = g_eh + (size_t)b * SB;
        K = DIM; lda = DIM; ldb = DIM;
    } else if (MODE == 1) {
        Ah = g_awh + (size_t)b * SB;
        Bh = g_eh + (size_t)b * SB;                                // [e][d] plain
        K = SEQ; lda = SEQ; ldb = DIM;
    } else {
        Ah = g_qh;  A2h = g_ch;      // rows indexed by global m (0..16383)
        Bh = g_wh;
        K = 2 * DIM; lda = DIM; ldb = 2 * DIM;
    }
    const int C = K >> 5;   // chunks of 32

#define LOAD_CHUNK(c, stg)                                                       \
    do {                                                                         \
        const int k0_ = (c) * 32;                                                \
        const __half* ah_; int ka_;                                              \
        if (MODE == 2 && k0_ >= DIM) { ah_ = A2h; ka_ = k0_ - DIM; }             \
        else                         { ah_ = Ah;  ka_ = k0_; }                   \
        const uint32_t sb_ = sm + (stg) * STAGEB;                                \
        _Pragma("unroll")                                                        \
        for (int i_ = 0; i_ < 2; i_++) {  /* A: 128 rows x 4 kc = 512 */         \
            int idx_ = i_ * 256 + tid;                                           \
            int row_ = idx_ >> 2, kc_ = idx_ & 3;                                \
            uint32_t d_ = swz(row_, kc_);                                        \
            cp16(sb_ + d_, (const char*)(ah_ + (size_t)(m0 + row_) * lda + ka_) + kc_ * 16); \
        }                                                                        \
        if (MODE == 1) {                                                         \
            /* B tile: 32 e-rows x 128B ([e][d] slice), 256 chunks */            \
            int row_ = tid >> 3, kc_ = tid & 7;                                  \
            uint32_t d_ = (uint32_t)(row_ * 128 + ((kc_ ^ (row_ & 7)) << 4));    \
            cp16(sb_ + OFFBH + d_, (const char*)(Bh + (size_t)(k0_ + row_) * ldb + n0) + kc_ * 16); \
        } else {                                                                 \
            /* B tile: 64 n-rows x 4 kc = 256 chunks */                          \
            int row_ = tid >> 2, kc_ = tid & 3;                                  \
            uint32_t d_ = swz(row_, kc_);                                        \
            cp16(sb_ + OFFBH + d_, (const char*)(Bh + (size_t)(n0 + row_) * ldb + k0_) + kc_ * 16); \
        }                                                                        \
    } while (0)

    // ---- per-lane ldmatrix address precomputes
    const int ar = lane & 15, ktop = lane >> 4;
    int aoff[2], axr[2];
#pragma unroll
    for (int mi = 0; mi < 2; mi++) {
        int row = wm * 32 + mi * 16 + ar;
        aoff[mi] = row * 64; axr[mi] = (row >> 1) & 3;
    }
    // NT B path (MODE 0/2): 2 groups of 16 n-rows per warp
    const int brl = ((lane >> 4) << 3) + (lane & 7);
    const int bk2 = (lane >> 3) & 1;
    int boff[2], bxr[2];
#pragma unroll
    for (int g = 0; g < 2; g++) {
        int nrow = wn * 32 + g * 16 + brl;
        boff[g] = nrow * 64; bxr[g] = (nrow >> 1) & 3;
    }
    // trans B path (MODE 1)
    const int tmt = lane >> 3, trl = lane & 7;
    const int te_base = ((tmt & 1) << 3) + trl;   // e-row within k16 group
    const int tkc_part = tmt >> 1;                // n8 selector

    float acc[2][4][4];
#pragma unroll
    for (int i = 0; i < 2; i++)
#pragma unroll
        for (int j = 0; j < 4; j++)
#pragma unroll
            for (int q = 0; q < 4; q++) acc[i][j][q] = 0.f;

    LOAD_CHUNK(0, 0); CP_COMMIT();
    LOAD_CHUNK(1, 1); CP_COMMIT();

    for (int c = 0; c < C; c++) {
        CP_WAIT1();
        __syncthreads();
        if (c + 2 < C) { LOAD_CHUNK(c + 2, (c + 2) % NSTAGE); }
        CP_COMMIT();
        const uint32_t sb = sm + (c % NSTAGE) * STAGEB;
#pragma unroll
        for (int ks = 0; ks < 2; ks++) {
            const int kb = ks * 2;
            uint32_t afr[2][4];
#pragma unroll
            for (int mi = 0; mi < 2; mi++)
                ldm4(afr[mi], sb + aoff[mi] + (((kb + ktop) ^ axr[mi]) << 4));
#pragma unroll
            for (int g = 0; g < 2; g++) {
                uint32_t bh[4];
                if (MODE == 1) {
                    const int e_r = ks * 16 + te_base;
                    const int kc = wn * 4 + g * 2 + tkc_part;
                    ldm4t(bh, sb + OFFBH + e_r * 128 + ((kc ^ trl) << 4));
                } else {
                    ldm4(bh, sb + OFFBH + boff[g] + (((kb + bk2) ^ bxr[g]) << 4));
                }
#pragma unroll
                for (int half = 0; half < 2; half++)
#pragma unroll
                    for (int mi = 0; mi < 2; mi++)
                        mma16816(acc[mi][g * 2 + half], afr[mi], &bh[half * 2]);
            }
        }
    }
#undef LOAD_CHUNK

    // ---- epilogue from registers
    const int qr = lane >> 2, qc = lane & 3;
#pragma unroll
    for (int mi = 0; mi < 2; mi++)
#pragma unroll
        for (int nj = 0; nj < 4; nj++)
#pragma unroll
            for (int half = 0; half < 2; half++) {
                const int row = m0 + wm * 32 + mi * 16 + qr + half * 8;
                const int col = n0 + wn * 32 + nj * 8 + qc * 2;
                const float v0 = acc[mi][nj][half * 2 + 0];
                const float v1 = acc[mi][nj][half * 2 + 1];
                if (MODE == 0) {
                    float2 o = make_float2(v0 * alpha, v1 * alpha);
                    *(float2*)(Cf + (size_t)b * SEQ * SEQ + (size_t)row * SEQ + col) = o;
                } else if (MODE == 1) {
                    __half2 H;
                    H.x = __float2half_rn(v0);
                    H.y = __float2half_rn(v1);
                    *(__half2*)(g_ch + (size_t)b * SB + (size_t)row * DIM + col) = H;
                } else {
                    const float mk = mask[row];
                    float2 o = make_float2(tanhf(v0 + bias[col]) * mk,
                                           tanhf(v1 + bias[col + 1]) * mk);
                    *(float2*)(Cf + (size_t)row * DIM + col) = o;
                }
            }
}

// ------ fp32 -> fp16 convert: Q, W, Enc fused in one grid (x4 vec) ----------
#define NQ4 (NELEM / 4)
#define NW4 (WELEM / 4)
#define NE4 (NELEM / 4)
__global__ __launch_bounds__(256) void k_split_all(const float4* __restrict__ Qs,
                                                   const float4* __restrict__ Ws,
                                                   const float4* __restrict__ Es)
{
    int i = blockIdx.x * 256 + threadIdx.x;
    const float4* src;
    uint2* hi;
    int j;
    if (i < NQ4) { src = Qs; hi = (uint2*)g_qh; j = i; }
    else if (i < NQ4 + NW4) { src = Ws; hi = (uint2*)g_wh; j = i - NQ4; }
    else if (i < NQ4 + NW4 + NE4) { src = Es; hi = (uint2*)g_eh; j = i - NQ4 - NW4; }
    else return;
    float4 v = src[j];
    union { __half h[4]; uint2 u; } H;
    H.h[0] = __float2half_rn(v.x);
    H.h[1] = __float2half_rn(v.y);
    H.h[2] = __float2half_rn(v.z);
    H.h[3] = __float2half_rn(v.w);
    hi[j] = H.u;
}

// ---------- softmax (in place, float4) + fp16 out ---------------------------
// 2 rows per block, 128 threads/row, 4 elements/thread.
__global__ __launch_bounds__(256) void k_softmax_split(float* __restrict__ w)
{
    const int g = threadIdx.x >> 7;
    const int r = threadIdx.x & 127;
    const size_t rowid = (size_t)blockIdx.x * 2 + g;
    float4* row = (float4*)(w + rowid * SEQ);
    float4 v = row[r];

    __shared__ float red[2][4];
    const int wl = (threadIdx.x >> 5) & 3;

    float m = fmaxf(fmaxf(v.x, v.y), fmaxf(v.z, v.w));
#pragma unroll
    for (int o = 16; o > 0; o >>= 1) m = fmaxf(m, __shfl_xor_sync(0xffffffffu, m, o));
    if ((threadIdx.x & 31) == 0) red[g][wl] = m;
    __syncthreads();
    const float M = fmaxf(fmaxf(red[g][0], red[g][1]), fmaxf(red[g][2], red[g][3]));
    __syncthreads();

    float4 e;
    e.x = __expf(v.x - M); e.y = __expf(v.y - M);
    e.z = __expf(v.z - M); e.w = __expf(v.w - M);
    float s = e.x + e.y + e.z + e.w;
#pragma unroll
    for (int o = 16; o > 0; o >>= 1) s += __shfl_xor_sync(0xffffffffu, s, o);
    if ((threadIdx.x & 31) == 0) red[g][wl] = s;
    __syncthreads();
    const float S = red[g][0] + red[g][1] + red[g][2] + red[g][3];
    const float inv = 1.0f / S;

    e.x *= inv; e.y *= inv; e.z *= inv; e.w *= inv;
    row[r] = e;

    union { __half h[4]; uint2 u; } H;
    H.h[0] = __float2half_rn(e.x);
    H.h[1] = __float2half_rn(e.y);
    H.h[2] = __float2half_rn(e.z);
    H.h[3] = __float2half_rn(e.w);
    ((uint2*)(g_awh + rowid * SEQ))[r] = H.u;
}

// ---------------------------------------------------------------------------
extern "C" void kernel_launch(void* const* d_in, const int* in_sizes, int n_in,
                              void* d_out, int out_size)
{
    const float* Q    = (const float*)d_in[0];
    const float* Enc  = (const float*)d_in[1];
    const float* mask = (const float*)d_in[2];
    const float* W    = (const float*)d_in[3];
    const float* bias = (const float*)d_in[4];

    float* out_masked  = (float*)d_out;
    float* out_weights = (float*)d_out + NELEM;

    static bool attr_done = false;
    if (!attr_done) {
        cudaFuncSetAttribute(k_gemm<0>, cudaFuncAttributeMaxDynamicSharedMemorySize, SMEM_DYN);
        cudaFuncSetAttribute(k_gemm<1>, cudaFuncAttributeMaxDynamicSharedMemorySize, SMEM_DYN);
        cudaFuncSetAttribute(k_gemm<2>, cudaFuncAttributeMaxDynamicSharedMemorySize, SMEM_DYN);
        attr_done = true;
    }

    const float alpha = 1.0f / sqrtf((float)DIM);

    // 1) one fused convert kernel (Q, W, Enc -> fp16)
    {
        int total = (int)(NQ4 + NW4 + NE4);
        k_split_all<<<(total + 255) / 256, 256>>>((const float4*)Q, (const float4*)W,
                                                  (const float4*)Enc);
    }
    // 2) scores = alpha * Q @ Enc^T -> out_weights (fp32)
    {
        dim3 g(SEQ / 64, SEQ / 128, BATCH);
        k_gemm<0><<<g, 256, SMEM_DYN>>>(out_weights, nullptr, nullptr, alpha);
    }
    // 3) softmax + fp16
    k_softmax_split<<<BATCH * SEQ / 2, 256>>>(out_weights);
    // 4) ctx = AW @ Enc (trans-B) -> g_ch (fp16)
    {
        dim3 g(DIM / 64, SEQ / 128, BATCH);
        k_gemm<1><<<g, 256, SMEM_DYN>>>(nullptr, nullptr, nullptr, 1.0f);
    }
    // 5) out = tanh([Q|ctx] @ W^T + bias) * mask
    {
        dim3 g(DIM / 64, (BATCH * SEQ) / 128, 1);
        k_gemm<2><<<g, 256, SMEM_DYN>>>(out_masked, bias, mask, 1.0f);
    }
}